// round 12
// baseline (speedup 1.0000x reference)
#include <cuda_runtime.h>
#include <cuda_fp16.h>
#include <cstdint>

#define BSZ  4
#define TSEQ 2048
#define CDIM 1024
#define HH   16
#define DHEAD 64
#define MROWS (BSZ*TSEQ)   // 8192
#define KDIM 1024

// ---------------- device scratch (allocation-free rule), all fp16 ----------------
__device__ __align__(16) __half g_q[(size_t)BSZ*HH*TSEQ*DHEAD];
__device__ __align__(16) __half g_k[(size_t)BSZ*HH*TSEQ*DHEAD];
__device__ __align__(16) __half g_v[(size_t)BSZ*HH*TSEQ*DHEAD];
__device__ __align__(16) __half g_att[(size_t)MROWS*CDIM];
__device__ __align__(16) __half g_xt[(size_t)MROWS*CDIM];       // x, fp16
__device__ __align__(16) __half g_wq[(size_t)3*CDIM*KDIM];      // w_qkv^T [N][K] fp16
__device__ __align__(16) __half g_wo[(size_t)CDIM*KDIM];        // w_out^T [N][K] fp16

// ---------------- helpers ----------------
__device__ __forceinline__ void mma16(float* d, const uint32_t* a, const uint32_t* b) {
    asm("mma.sync.aligned.m16n8k16.row.col.f32.f16.f16.f32 "
        "{%0,%1,%2,%3}, {%4,%5,%6,%7}, {%8,%9}, {%0,%1,%2,%3};"
        : "+f"(d[0]), "+f"(d[1]), "+f"(d[2]), "+f"(d[3])
        : "r"(a[0]), "r"(a[1]), "r"(a[2]), "r"(a[3]), "r"(b[0]), "r"(b[1]));
}

__device__ __forceinline__ void ldsm4(uint32_t& r0, uint32_t& r1, uint32_t& r2, uint32_t& r3,
                                      uint32_t addr) {
    asm volatile("ldmatrix.sync.aligned.m8n8.x4.shared.b16 {%0,%1,%2,%3}, [%4];"
                 : "=r"(r0), "=r"(r1), "=r"(r2), "=r"(r3) : "r"(addr));
}

__device__ __forceinline__ void ldsm4t(uint32_t& r0, uint32_t& r1, uint32_t& r2, uint32_t& r3,
                                       uint32_t addr) {
    asm volatile("ldmatrix.sync.aligned.m8n8.x4.trans.shared.b16 {%0,%1,%2,%3}, [%4];"
                 : "=r"(r0), "=r"(r1), "=r"(r2), "=r"(r3) : "r"(addr));
}

__device__ __forceinline__ uint32_t smem_u32(const void* p) {
    uint32_t a;
    asm("{ .reg .u64 t; cvta.to.shared.u64 t, %1; cvt.u32.u64 %0, t; }" : "=r"(a) : "l"(p));
    return a;
}

__device__ __forceinline__ void cp16(uint32_t s, const void* g) {
    asm volatile("cp.async.cg.shared.global [%0], [%1], 16;" :: "r"(s), "l"(g));
}
#define CP_COMMIT() asm volatile("cp.async.commit_group;" ::: "memory")
#define CP_WAIT1()  asm volatile("cp.async.wait_group 1;" ::: "memory")
#define CP_WAIT0()  asm volatile("cp.async.wait_group 0;" ::: "memory")

__device__ __forceinline__ uint32_t pack_h2(float a, float b) {
    __half2 h = __floats2half2_rn(a, b);
    return *(uint32_t*)&h;
}

// ---------------- x: f32 -> f16 ----------------
__global__ __launch_bounds__(256)
void cvtx_kernel(const float4* __restrict__ src, uint2* __restrict__ dst, int n4)
{
    const int i = blockIdx.x * 256 + threadIdx.x;
    if (i < n4) {
        float4 v = src[i];
        dst[i] = make_uint2(pack_h2(v.x, v.y), pack_h2(v.z, v.w));
    }
}

// ---------------- weight: f32 [R][C] -> f16 transposed [C][R] ----------------
__global__ __launch_bounds__(256)
void cvtw_kernel(const float* __restrict__ src, __half* __restrict__ dst, int R, int C)
{
    __shared__ float t[32][33];
    const int c0 = blockIdx.x * 32, r0 = blockIdx.y * 32;
    const int tx = threadIdx.x, ty = threadIdx.y;
#pragma unroll
    for (int i = 0; i < 4; i++)
        t[ty + 8*i][tx] = src[(size_t)(r0 + ty + 8*i) * C + c0 + tx];
    __syncthreads();
#pragma unroll
    for (int i = 0; i < 4; i++)
        dst[(size_t)(c0 + ty + 8*i) * R + r0 + tx] = __float2half_rn(t[tx][ty + 8*i]);
}

// ---------------- fp16 mma.sync GEMM: CTA 256x128, warp tile 64x64, BK=64 ----------------
// 256 thr = 8 warps (4m x 2n). Smem rows stride 72 halves, ldmatrix conflict-free.
#define BK 64
#define MA_STR 72
#define MA_H (256*MA_STR)               // 18432 halves (A tile)
#define MB_H (128*MA_STR)               // 9216 halves (B tile)
#define ST_H (MA_H + MB_H)              // 27648 halves = 55296 B
#define STAGES 3
#define MM_SMEM (STAGES*ST_H*2)         // 165888 B -> 1 CTA/SM

__global__ __launch_bounds__(256, 1)
void mm_kernel(const __half* __restrict__ A, const __half* __restrict__ Bt,
               const float* __restrict__ bias, float* __restrict__ Cout,
               int N, int mode)
{
    extern __shared__ __half smh[];
    const uint32_t sb = smem_u32(smh);

    const int tid  = threadIdx.x;
    const int lane = tid & 31;
    const int warp = tid >> 5;
    const int wm = (warp >> 1) * 64;      // 0,64,128,192
    const int wn = (warp & 1) * 64;       // 0,64
    const int g  = lane >> 2;
    const int ig = lane & 3;

    const int m0 = blockIdx.y * 256;
    const int n0 = blockIdx.x * 128;

    if (mode) A = g_att;

    // per-lane ldmatrix offsets (halves -> bytes)
    const uint32_t aoff = ((wm + (lane & 15)) * MA_STR + (lane >> 4) * 8) * 2;
    const uint32_t boff = ((wn + (lane & 15)) * MA_STR + (lane >> 4) * 8) * 2;

    float d[4][8][4];
#pragma unroll
    for (int mt = 0; mt < 4; mt++)
#pragma unroll
        for (int nt = 0; nt < 8; nt++)
#pragma unroll
            for (int r = 0; r < 4; r++) d[mt][nt][r] = 0.f;

    // A tile: 256 rows x 8 chunks(16B) = 2048 cp16 (8/thread); B: 128 x 8 = 1024 (4/thread)
#define LDG_ASYNC(c, st) do {                                                     \
    uint32_t _sa = sb + (st)*ST_H*2;                                              \
    uint32_t _sb2 = _sa + MA_H*2;                                                 \
    _Pragma("unroll") for (int i = 0; i < 8; i++) {                               \
        int idx = tid + 256*i; int row = idx >> 3, c8 = idx & 7;                  \
        cp16(_sa + (row*MA_STR + c8*8)*2,                                         \
             A + (size_t)(m0 + row)*KDIM + (c)*BK + c8*8); }                      \
    _Pragma("unroll") for (int i = 0; i < 4; i++) {                               \
        int idx = tid + 256*i; int row = idx >> 3, c8 = idx & 7;                  \
        cp16(_sb2 + (row*MA_STR + c8*8)*2,                                        \
             Bt + (size_t)(n0 + row)*KDIM + (c)*BK + c8*8); }                     \
} while (0)

#define COMPUTE(st) do {                                                          \
    const uint32_t _ab = sb + (st)*ST_H*2 + aoff;                                 \
    const uint32_t _bb = sb + (st)*ST_H*2 + MA_H*2 + boff;                        \
    _Pragma("unroll") for (int s = 0; s < 4; s++) {                               \
        const int k0 = s*16;                                                      \
        uint32_t af[4][4], bf[4][4];                                              \
        _Pragma("unroll") for (int mt = 0; mt < 4; mt++)                          \
            ldsm4(af[mt][0], af[mt][1], af[mt][2], af[mt][3],                     \
                  _ab + (mt*16*MA_STR + k0)*2);                                   \
        _Pragma("unroll") for (int p = 0; p < 4; p++)                             \
            ldsm4(bf[p][0], bf[p][1], bf[p][2], bf[p][3],                         \
                  _bb + (p*16*MA_STR + k0)*2);                                    \
        _Pragma("unroll") for (int mt = 0; mt < 4; mt++)                          \
            _Pragma("unroll") for (int p = 0; p < 4; p++) {                       \
                uint32_t b0[2] = { bf[p][0], bf[p][2] };                          \
                uint32_t b1[2] = { bf[p][1], bf[p][3] };                          \
                mma16(d[mt][2*p],   af[mt], b0);                                  \
                mma16(d[mt][2*p+1], af[mt], b1);                                  \
            }                                                                     \
    }                                                                             \
} while (0)

    LDG_ASYNC(0, 0); CP_COMMIT();
    LDG_ASYNC(1, 1); CP_COMMIT();

#pragma unroll 1
    for (int c = 0; c < KDIM/BK; c++) {
        CP_WAIT1();
        __syncthreads();
        if (c + 2 < KDIM/BK) {
            const int st = (c + 2) % STAGES;
            LDG_ASYNC(c + 2, st);
        }
        CP_COMMIT();
        COMPUTE(c % STAGES);
    }

#pragma unroll
    for (int mt = 0; mt < 4; mt++) {
        const int r0 = m0 + wm + mt*16 + g;
#pragma unroll
        for (int nt = 0; nt < 8; nt++) {
            const int c0 = n0 + wn + nt*8 + ig*2;
            const float b0 = bias[c0], b1 = bias[c0+1];
            if (mode == 0) {
                const int sec = c0 >> 10;
                const int h   = (c0 & 1023) >> 6;
                const int dd  = c0 & 63;
                __half* dstp = (sec == 0) ? g_q : ((sec == 1) ? g_k : g_v);
                const float scale = (sec == 0) ? 0.125f : 1.0f;
#pragma unroll
                for (int rr = 0; rr < 2; rr++) {
                    const int r = r0 + rr*8;
                    const int b = r >> 11, t = r & 2047;
                    uint32_t v = pack_h2((d[mt][nt][rr*2+0] + b0) * scale,
                                         (d[mt][nt][rr*2+1] + b1) * scale);
                    *(uint32_t*)(dstp + (((size_t)(b*HH + h))*TSEQ + t)*DHEAD + dd) = v;
                }
            } else {
#pragma unroll
                for (int rr = 0; rr < 2; rr++) {
                    const int r = r0 + rr*8;
                    float2 v = make_float2(d[mt][nt][rr*2+0] + b0, d[mt][nt][rr*2+1] + b1);
                    *(float2*)(Cout + (size_t)r*N + c0) = v;
                }
            }
        }
    }
}

// ---------------- fp16 flash attention: BM=128 (8 warps x 16 rows), BN=64 ----------------
#define AT_STR 72
#define QP_H (128*AT_STR)               // 9216 halves (Q or P tile)
#define KV_H (64*AT_STR)                // 4608 halves per K/V tile
#define AT_SMEM ((2*QP_H + 4*KV_H)*2)   // 73728 B -> 2 CTA/SM

__global__ __launch_bounds__(256, 2)
void attn_kernel()
{
    extern __shared__ __half smh[];
    __half* Qs  = smh;
    __half* Ps  = Qs + QP_H;
    __half* Kst = Ps + QP_H;             // 2 stages
    __half* Vst = Kst + 2*KV_H;          // 2 stages
    const uint32_t sb_k = smem_u32(Kst);
    const uint32_t sb_v = smem_u32(Vst);

    const int tid  = threadIdx.x;
    const int lane = tid & 31;
    const int w    = tid >> 5;           // 0..7
    const int g    = lane >> 2;
    const int ig   = lane & 3;
    const int bh = blockIdx.y;
    const int qi = (gridDim.x - 1) - blockIdx.x;   // long blocks first
    const int q0 = qi * 128;
    const int jmax = 2*qi + 1;

    const __half* Qg = g_q + (size_t)bh * TSEQ * DHEAD;
    const __half* Kg = g_k + (size_t)bh * TSEQ * DHEAD;
    const __half* Vg = g_v + (size_t)bh * TSEQ * DHEAD;

    // K/V tile: 64 rows x 8 chunks = 512 cp16 each; 256 thr -> 2/thread
#define PREFETCH_KV(j0, st) do {                                                  \
    uint32_t _kb = sb_k + (st)*KV_H*2;                                            \
    uint32_t _vb = sb_v + (st)*KV_H*2;                                            \
    _Pragma("unroll") for (int i = 0; i < 2; i++) {                               \
        int f = tid + 256*i; int row = f >> 3, c8 = f & 7;                        \
        cp16(_kb + (row*AT_STR + c8*8)*2, Kg + (size_t)((j0)+row)*DHEAD + c8*8);  \
        cp16(_vb + (row*AT_STR + c8*8)*2, Vg + (size_t)((j0)+row)*DHEAD + c8*8);  \
    }                                                                             \
} while (0)

    // Q tile (128 rows): raw copy (already scaled fp16)
#pragma unroll
    for (int i = 0; i < 4; i++) {
        const int f = tid + 256*i;
        const int row = f >> 3, c8 = f & 7;
        *(uint4*)(Qs + row*AT_STR + c8*8) =
            *(const uint4*)(Qg + (size_t)(q0+row)*DHEAD + c8*8);
    }

    PREFETCH_KV(0, 0);
    CP_COMMIT();

    const int r0 = 16*w + g;             // 0..127
    float O[8][4];
#pragma unroll
    for (int nt = 0; nt < 8; nt++)
#pragma unroll
        for (int r = 0; r < 4; r++) O[nt][r] = 0.f;
    float m0 = -1e30f, m1 = -1e30f, l0 = 0.f, l1 = 0.f;

    const int mi  = lane >> 3;
    const int rin = lane & 7;
    const int v_row_off = ((mi & 1) ? 8 : 0) + rin;
    const int v_col_off = (mi >> 1) ? 8 : 0;

#pragma unroll 1
    for (int jt = 0; jt <= jmax; jt++) {
        const int j0 = jt * 64;
        const int p = jt & 1;

        CP_WAIT0();
        __syncthreads();

        if (jt < jmax) {
            PREFETCH_KV(j0 + 64, p ^ 1);
            CP_COMMIT();
        }

        const __half* Ks = Kst + p*KV_H;
        const uint32_t vbase = sb_v + p*KV_H*2;

        // S = Q K^T  (16x64 per warp)
        float s[8][4];
#pragma unroll
        for (int nt = 0; nt < 8; nt++)
#pragma unroll
            for (int r = 0; r < 4; r++) s[nt][r] = 0.f;

#pragma unroll
        for (int k0 = 0; k0 < 64; k0 += 16) {
            uint32_t a[4];
            a[0] = *(const uint32_t*)(Qs + r0*AT_STR + k0 + 2*ig);
            a[1] = *(const uint32_t*)(Qs + (r0+8)*AT_STR + k0 + 2*ig);
            a[2] = *(const uint32_t*)(Qs + r0*AT_STR + k0 + 8 + 2*ig);
            a[3] = *(const uint32_t*)(Qs + (r0+8)*AT_STR + k0 + 8 + 2*ig);
#pragma unroll
            for (int nt = 0; nt < 8; nt++) {
                uint32_t b[2];
                b[0] = *(const uint32_t*)(Ks + (nt*8+g)*AT_STR + k0 + 2*ig);
                b[1] = *(const uint32_t*)(Ks + (nt*8+g)*AT_STR + k0 + 8 + 2*ig);
                mma16(s[nt], a, b);
            }
        }

        // causal mask (last two tiles overlap the diagonal)
        if (jt >= 2*qi) {
            const int qa = q0 + r0, qb = qa + 8;
#pragma unroll
            for (int nt = 0; nt < 8; nt++) {
                const int j = j0 + nt*8 + 2*ig;
                if (j     > qa) s[nt][0] = -1e30f;
                if (j + 1 > qa) s[nt][1] = -1e30f;
                if (j     > qb) s[nt][2] = -1e30f;
                if (j + 1 > qb) s[nt][3] = -1e30f;
            }
        }

        float a0 = -1e30f, a1 = -1e30f;
#pragma unroll
        for (int nt = 0; nt < 8; nt++) {
            a0 = fmaxf(a0, fmaxf(s[nt][0], s[nt][1]));
            a1 = fmaxf(a1, fmaxf(s[nt][2], s[nt][3]));
        }
        a0 = fmaxf(a0, __shfl_xor_sync(0xFFFFFFFFu, a0, 1));
        a0 = fmaxf(a0, __shfl_xor_sync(0xFFFFFFFFu, a0, 2));
        a1 = fmaxf(a1, __shfl_xor_sync(0xFFFFFFFFu, a1, 1));
        a1 = fmaxf(a1, __shfl_xor_sync(0xFFFFFFFFu, a1, 2));

        const float mn0 = fmaxf(m0, a0), mn1 = fmaxf(m1, a1);
        const float c0 = __expf(m0 - mn0), c1 = __expf(m1 - mn1);
        l0 *= c0; l1 *= c1;
#pragma unroll
        for (int nt = 0; nt < 8; nt++) {
            O[nt][0] *= c0; O[nt][1] *= c0;
            O[nt][2] *= c1; O[nt][3] *= c1;
        }

        float t0 = 0.f, t1 = 0.f;
#pragma unroll
        for (int nt = 0; nt < 8; nt++) {
            const float p0 = __expf(s[nt][0] - mn0);
            const float p1 = __expf(s[nt][1] - mn0);
            const float p2 = __expf(s[nt][2] - mn1);
            const float p3 = __expf(s[nt][3] - mn1);
            t0 += p0 + p1; t1 += p2 + p3;
            *(uint32_t*)(Ps + r0*AT_STR + nt*8 + 2*ig)     = pack_h2(p0, p1);
            *(uint32_t*)(Ps + (r0+8)*AT_STR + nt*8 + 2*ig) = pack_h2(p2, p3);
        }
        t0 += __shfl_xor_sync(0xFFFFFFFFu, t0, 1);
        t0 += __shfl_xor_sync(0xFFFFFFFFu, t0, 2);
        t1 += __shfl_xor_sync(0xFFFFFFFFu, t1, 1);
        t1 += __shfl_xor_sync(0xFFFFFFFFu, t1, 2);
        l0 += t0; l1 += t1;
        m0 = mn0; m1 = mn1;
        __syncwarp();

        // O += P @ V (per-warp P rows; warp-local sync only)
#pragma unroll
        for (int k0 = 0; k0 < 64; k0 += 16) {
            uint32_t a[4];
            a[0] = *(const uint32_t*)(Ps + r0*AT_STR + k0 + 2*ig);
            a[1] = *(const uint32_t*)(Ps + (r0+8)*AT_STR + k0 + 2*ig);
            a[2] = *(const uint32_t*)(Ps + r0*AT_STR + k0 + 8 + 2*ig);
            a[3] = *(const uint32_t*)(Ps + (r0+8)*AT_STR + k0 + 8 + 2*ig);
#pragma unroll
            for (int nn = 0; nn < 4; nn++) {
                uint32_t b0, b1, b2, b3;
                ldsm4t(b0, b1, b2, b3,
                       vbase + ((k0 + v_row_off)*AT_STR + nn*16 + v_col_off)*2);
                uint32_t bA[2] = { b0, b1 };
                uint32_t bB[2] = { b2, b3 };
                mma16(O[2*nn],   a, bA);
                mma16(O[2*nn+1], a, bB);
            }
        }
        __syncwarp();
    }

    // normalize, write g_att as fp16
    const float inv0 = 1.f / l0, inv1 = 1.f / l1;
    const int b = bh >> 4, h = bh & 15;
    __half* base = g_att + ((size_t)(b*TSEQ + q0 + r0))*CDIM + h*DHEAD;
#pragma unroll
    for (int nt = 0; nt < 8; nt++) {
        *(uint32_t*)(base + nt*8 + 2*ig) =
            pack_h2(O[nt][0]*inv0, O[nt][1]*inv0);
        *(uint32_t*)(base + (size_t)8*CDIM + nt*8 + 2*ig) =
            pack_h2(O[nt][2]*inv1, O[nt][3]*inv1);
    }
}

// ---------------- launch ----------------
extern "C" void kernel_launch(void* const* d_in, const int* in_sizes, int n_in,
                              void* d_out, int out_size)
{
    (void)in_sizes; (void)n_in; (void)out_size;
    const float* x     = (const float*)d_in[0];
    const float* w_qkv = (const float*)d_in[1];
    const float* b_qkv = (const float*)d_in[2];
    const float* w_out = (const float*)d_in[3];
    const float* b_out = (const float*)d_in[4];
    float* out = (float*)d_out;

    cudaFuncSetAttribute(mm_kernel,   cudaFuncAttributeMaxDynamicSharedMemorySize, MM_SMEM);
    cudaFuncSetAttribute(attn_kernel, cudaFuncAttributeMaxDynamicSharedMemorySize, AT_SMEM);

    __half *xt, *wq, *wo;
    cudaGetSymbolAddress((void**)&xt, g_xt);
    cudaGetSymbolAddress((void**)&wq, g_wq);
    cudaGetSymbolAddress((void**)&wo, g_wo);

    // 0) one-shot fp16 conversion (x) and transpose+conversion (weights -> [N][K])
    cvtx_kernel<<<(MROWS*CDIM/4 + 255)/256, 256>>>((const float4*)x, (uint2*)xt, MROWS*CDIM/4);
    cvtw_kernel<<<dim3(3072/32, 1024/32), dim3(32, 8)>>>(w_qkv, wq, 1024, 3072);
    cvtw_kernel<<<dim3(1024/32, 1024/32), dim3(32, 8)>>>(w_out, wo, 1024, 1024);

    // 1) QKV projection + bias + head-split scatter (fp16 Q/K/V, Q pre-scaled)
    mm_kernel<<<dim3(3072/128, MROWS/256), 256, MM_SMEM>>>(xt, wq, b_qkv, nullptr, 3072, 0);
    // 2) causal flash attention (fp16, BM=128, cp.async double-buffered K/V)
    attn_kernel<<<dim3(TSEQ/128, BSZ*HH), 256, AT_SMEM>>>();
    // 3) output projection + bias (fp32 out)
    mm_kernel<<<dim3(1024/128, MROWS/256), 256, MM_SMEM>>>(nullptr, wo, b_out, out, 1024, 1);
}

// round 13
// speedup vs baseline: 1.0945x; 1.0945x over previous
#include <cuda_runtime.h>
#include <cuda_fp16.h>
#include <cstdint>

#define BSZ  4
#define TSEQ 2048
#define CDIM 1024
#define HH   16
#define DHEAD 64
#define MROWS (BSZ*TSEQ)   // 8192
#define KDIM 1024

// ---------------- device scratch (allocation-free rule), all fp16 ----------------
__device__ __align__(16) __half g_q[(size_t)BSZ*HH*TSEQ*DHEAD];
__device__ __align__(16) __half g_k[(size_t)BSZ*HH*TSEQ*DHEAD];
__device__ __align__(16) __half g_v[(size_t)BSZ*HH*TSEQ*DHEAD];
__device__ __align__(16) __half g_att[(size_t)MROWS*CDIM];
__device__ __align__(16) __half g_xt[(size_t)MROWS*CDIM];       // x, fp16
__device__ __align__(16) __half g_wq[(size_t)3*CDIM*KDIM];      // w_qkv^T [N][K] fp16
__device__ __align__(16) __half g_wo[(size_t)CDIM*KDIM];        // w_out^T [N][K] fp16

// ---------------- helpers ----------------
__device__ __forceinline__ void mma16(float* d, const uint32_t* a, const uint32_t* b) {
    asm("mma.sync.aligned.m16n8k16.row.col.f32.f16.f16.f32 "
        "{%0,%1,%2,%3}, {%4,%5,%6,%7}, {%8,%9}, {%0,%1,%2,%3};"
        : "+f"(d[0]), "+f"(d[1]), "+f"(d[2]), "+f"(d[3])
        : "r"(a[0]), "r"(a[1]), "r"(a[2]), "r"(a[3]), "r"(b[0]), "r"(b[1]));
}

__device__ __forceinline__ void ldsm4(uint32_t& r0, uint32_t& r1, uint32_t& r2, uint32_t& r3,
                                      uint32_t addr) {
    asm volatile("ldmatrix.sync.aligned.m8n8.x4.shared.b16 {%0,%1,%2,%3}, [%4];"
                 : "=r"(r0), "=r"(r1), "=r"(r2), "=r"(r3) : "r"(addr));
}

__device__ __forceinline__ void ldsm4t(uint32_t& r0, uint32_t& r1, uint32_t& r2, uint32_t& r3,
                                       uint32_t addr) {
    asm volatile("ldmatrix.sync.aligned.m8n8.x4.trans.shared.b16 {%0,%1,%2,%3}, [%4];"
                 : "=r"(r0), "=r"(r1), "=r"(r2), "=r"(r3) : "r"(addr));
}

__device__ __forceinline__ uint32_t smem_u32(const void* p) {
    uint32_t a;
    asm("{ .reg .u64 t; cvta.to.shared.u64 t, %1; cvt.u32.u64 %0, t; }" : "=r"(a) : "l"(p));
    return a;
}

__device__ __forceinline__ void cp16(uint32_t s, const void* g) {
    asm volatile("cp.async.cg.shared.global [%0], [%1], 16;" :: "r"(s), "l"(g));
}
#define CP_COMMIT() asm volatile("cp.async.commit_group;" ::: "memory")
#define CP_WAIT1()  asm volatile("cp.async.wait_group 1;" ::: "memory")
#define CP_WAIT0()  asm volatile("cp.async.wait_group 0;" ::: "memory")

__device__ __forceinline__ uint32_t pack_h2(float a, float b) {
    __half2 h = __floats2half2_rn(a, b);
    return *(uint32_t*)&h;
}

// ---------------- x: f32 -> f16 ----------------
__global__ __launch_bounds__(256)
void cvtx_kernel(const float4* __restrict__ src, uint2* __restrict__ dst, int n4)
{
    const int i = blockIdx.x * 256 + threadIdx.x;
    if (i < n4) {
        float4 v = src[i];
        dst[i] = make_uint2(pack_h2(v.x, v.y), pack_h2(v.z, v.w));
    }
}

// ---------------- weight: f32 [R][C] -> f16 transposed [C][R] ----------------
__global__ __launch_bounds__(256)
void cvtw_kernel(const float* __restrict__ src, __half* __restrict__ dst, int R, int C)
{
    __shared__ float t[32][33];
    const int c0 = blockIdx.x * 32, r0 = blockIdx.y * 32;
    const int tx = threadIdx.x, ty = threadIdx.y;
#pragma unroll
    for (int i = 0; i < 4; i++)
        t[ty + 8*i][tx] = src[(size_t)(r0 + ty + 8*i) * C + c0 + tx];
    __syncthreads();
#pragma unroll
    for (int i = 0; i < 4; i++)
        dst[(size_t)(c0 + ty + 8*i) * R + r0 + tx] = __float2half_rn(t[tx][ty + 8*i]);
}

// ---------------- fp16 mma.sync GEMM (R11 config: CTA 128x128, BK=64, 2 CTA/SM) ----------------
#define BK 64
#define MA_STR 72
#define MA_H (128*MA_STR)               // 9216 halves per tile
#define ST_H (2*MA_H)                   // 18432 halves = 36864 B
#define STAGES 3
#define MM_SMEM (STAGES*ST_H*2)         // 110592 B

__global__ __launch_bounds__(256, 2)
void mm_kernel(const __half* __restrict__ A, const __half* __restrict__ Bt,
               const float* __restrict__ bias, float* __restrict__ Cout,
               int N, int mode)
{
    extern __shared__ __half smh[];
    const uint32_t sb = smem_u32(smh);

    const int tid  = threadIdx.x;
    const int lane = tid & 31;
    const int warp = tid >> 5;
    const int wm = (warp >> 2) * 64;
    const int wn = (warp & 3) * 32;
    const int g  = lane >> 2;
    const int ig = lane & 3;

    const int m0 = blockIdx.y * 128;
    const int n0 = blockIdx.x * 128;

    if (mode) A = g_att;

    const uint32_t aoff = ((wm + (lane & 15)) * MA_STR + (lane >> 4) * 8) * 2;
    const uint32_t boff = ((wn + (lane & 15)) * MA_STR + (lane >> 4) * 8) * 2;

    float d[4][4][4];
#pragma unroll
    for (int mt = 0; mt < 4; mt++)
#pragma unroll
        for (int nt = 0; nt < 4; nt++)
#pragma unroll
            for (int r = 0; r < 4; r++) d[mt][nt][r] = 0.f;

#define LDG_ASYNC(c, st) do {                                                     \
    uint32_t _sa = sb + (st)*ST_H*2;                                              \
    uint32_t _sb2 = _sa + MA_H*2;                                                 \
    _Pragma("unroll") for (int i = 0; i < 4; i++) {                               \
        int idx = tid + 256*i; int row = idx >> 3, c8 = idx & 7;                  \
        cp16(_sa + (row*MA_STR + c8*8)*2,                                         \
             A + (size_t)(m0 + row)*KDIM + (c)*BK + c8*8); }                      \
    _Pragma("unroll") for (int i = 0; i < 4; i++) {                               \
        int idx = tid + 256*i; int row = idx >> 3, c8 = idx & 7;                  \
        cp16(_sb2 + (row*MA_STR + c8*8)*2,                                        \
             Bt + (size_t)(n0 + row)*KDIM + (c)*BK + c8*8); }                     \
} while (0)

#define COMPUTE(st) do {                                                          \
    const uint32_t _ab = sb + (st)*ST_H*2 + aoff;                                 \
    const uint32_t _bb = sb + (st)*ST_H*2 + MA_H*2 + boff;                        \
    _Pragma("unroll") for (int s = 0; s < 4; s++) {                               \
        const int k0 = s*16;                                                      \
        uint32_t af[4][4], bf[2][4];                                              \
        _Pragma("unroll") for (int mt = 0; mt < 4; mt++)                          \
            ldsm4(af[mt][0], af[mt][1], af[mt][2], af[mt][3],                     \
                  _ab + (mt*16*MA_STR + k0)*2);                                   \
        _Pragma("unroll") for (int p = 0; p < 2; p++)                             \
            ldsm4(bf[p][0], bf[p][1], bf[p][2], bf[p][3],                         \
                  _bb + (p*16*MA_STR + k0)*2);                                    \
        _Pragma("unroll") for (int mt = 0; mt < 4; mt++)                          \
            _Pragma("unroll") for (int p = 0; p < 2; p++) {                       \
                uint32_t b0[2] = { bf[p][0], bf[p][2] };                          \
                uint32_t b1[2] = { bf[p][1], bf[p][3] };                          \
                mma16(d[mt][2*p],   af[mt], b0);                                  \
                mma16(d[mt][2*p+1], af[mt], b1);                                  \
            }                                                                     \
    }                                                                             \
} while (0)

    LDG_ASYNC(0, 0); CP_COMMIT();
    LDG_ASYNC(1, 1); CP_COMMIT();

#pragma unroll 1
    for (int c = 0; c < KDIM/BK; c++) {
        CP_WAIT1();
        __syncthreads();
        if (c + 2 < KDIM/BK) {
            const int st = (c + 2) % STAGES;
            LDG_ASYNC(c + 2, st);
        }
        CP_COMMIT();
        COMPUTE(c % STAGES);
    }

#pragma unroll
    for (int mt = 0; mt < 4; mt++) {
        const int r0 = m0 + wm + mt*16 + g;
#pragma unroll
        for (int nt = 0; nt < 4; nt++) {
            const int c0 = n0 + wn + nt*8 + ig*2;
            const float b0 = bias[c0], b1 = bias[c0+1];
            if (mode == 0) {
                const int sec = c0 >> 10;
                const int h   = (c0 & 1023) >> 6;
                const int dd  = c0 & 63;
                __half* dstp = (sec == 0) ? g_q : ((sec == 1) ? g_k : g_v);
                const float scale = (sec == 0) ? 0.125f : 1.0f;
#pragma unroll
                for (int rr = 0; rr < 2; rr++) {
                    const int r = r0 + rr*8;
                    const int b = r >> 11, t = r & 2047;
                    uint32_t v = pack_h2((d[mt][nt][rr*2+0] + b0) * scale,
                                         (d[mt][nt][rr*2+1] + b1) * scale);
                    *(uint32_t*)(dstp + (((size_t)(b*HH + h))*TSEQ + t)*DHEAD + dd) = v;
                }
            } else {
#pragma unroll
                for (int rr = 0; rr < 2; rr++) {
                    const int r = r0 + rr*8;
                    float2 v = make_float2(d[mt][nt][rr*2+0] + b0, d[mt][nt][rr*2+1] + b1);
                    *(float2*)(Cout + (size_t)r*N + c0) = v;
                }
            }
        }
    }
}

// ---------------- fp16 flash attention (R11 shape: BM=64, 128 thr) + ldmatrix frags ----------------
#define AT_STR 72
#define T_H (64*AT_STR)                 // 4608 halves = 9216 B per tile
#define AT_SMEM ((6*T_H)*2)             // Q + P + 2K + 2V = 55296 B

__global__ __launch_bounds__(128, 3)
void attn_kernel()
{
    extern __shared__ __half smh[];
    __half* Qs  = smh;
    __half* Ps  = Qs + T_H;
    __half* Kst = Ps + T_H;
    __half* Vst = Kst + 2*T_H;
    const uint32_t sb_q = smem_u32(Qs);
    const uint32_t sb_p = smem_u32(Ps);
    const uint32_t sb_k = smem_u32(Kst);
    const uint32_t sb_v = smem_u32(Vst);

    const int tid  = threadIdx.x;
    const int lane = tid & 31;
    const int w    = tid >> 5;
    const int g    = lane >> 2;
    const int ig   = lane & 3;
    const int bh = blockIdx.y;
    const int qt = (gridDim.x - 1) - blockIdx.x;   // long blocks first
    const int q0 = qt * 64;

    const __half* Qg = g_q + (size_t)bh * TSEQ * DHEAD;
    const __half* Kg = g_k + (size_t)bh * TSEQ * DHEAD;
    const __half* Vg = g_v + (size_t)bh * TSEQ * DHEAD;

    // a-frag ldmatrix offset (Q / P, tile rows 16w..16w+15)
    const uint32_t aoff = ((16*w + (lane & 15)) * AT_STR + (lane >> 4) * 8) * 2;
    // K b-frag ldmatrix offset (rows lane&15, col-half lane>>4)
    const uint32_t koff = (((lane & 15)) * AT_STR + (lane >> 4) * 8) * 2;

#define PREFETCH_KV(j0, st) do {                                                  \
    uint32_t _kb = sb_k + (st)*T_H*2;                                             \
    uint32_t _vb = sb_v + (st)*T_H*2;                                             \
    _Pragma("unroll") for (int i = 0; i < 4; i++) {                               \
        int f = tid + 128*i; int row = f >> 3, c8 = f & 7;                        \
        cp16(_kb + (row*AT_STR + c8*8)*2, Kg + (size_t)((j0)+row)*DHEAD + c8*8);  \
        cp16(_vb + (row*AT_STR + c8*8)*2, Vg + (size_t)((j0)+row)*DHEAD + c8*8);  \
    }                                                                             \
} while (0)

    // Q tile: raw copy (already scaled fp16)
#pragma unroll
    for (int i = 0; i < 4; i++) {
        const int f = tid + 128*i;
        const int row = f >> 3, c8 = f & 7;
        *(uint4*)(Qs + row*AT_STR + c8*8) =
            *(const uint4*)(Qg + (size_t)(q0+row)*DHEAD + c8*8);
    }

    PREFETCH_KV(0, 0);
    CP_COMMIT();

    const int r0 = 16*w + g;
    float O[8][4];
#pragma unroll
    for (int nt = 0; nt < 8; nt++)
#pragma unroll
        for (int r = 0; r < 4; r++) O[nt][r] = 0.f;
    float m0 = -1e30f, m1 = -1e30f, l0 = 0.f, l1 = 0.f;

    const int mi  = lane >> 3;
    const int rin = lane & 7;
    const int v_row_off = ((mi & 1) ? 8 : 0) + rin;
    const int v_col_off = (mi >> 1) ? 8 : 0;

#pragma unroll 1
    for (int jt = 0; jt <= qt; jt++) {
        const int j0 = jt * 64;
        const int p = jt & 1;

        CP_WAIT0();
        __syncthreads();

        if (jt < qt) {
            PREFETCH_KV(j0 + 64, p ^ 1);
            CP_COMMIT();
        }

        const uint32_t kbase = sb_k + p*T_H*2 + koff;
        const uint32_t vbase = sb_v + p*T_H*2;

        // S = Q K^T  (16x64 per warp) — ldmatrix frags
        float s[8][4];
#pragma unroll
        for (int nt = 0; nt < 8; nt++)
#pragma unroll
            for (int r = 0; r < 4; r++) s[nt][r] = 0.f;

#pragma unroll
        for (int k0 = 0; k0 < 64; k0 += 16) {
            uint32_t a[4];
            ldsm4(a[0], a[1], a[2], a[3], sb_q + aoff + k0*2);
#pragma unroll
            for (int pp = 0; pp < 4; pp++) {
                uint32_t bf0, bf1, bf2, bf3;
                ldsm4(bf0, bf1, bf2, bf3, kbase + (pp*16*AT_STR + k0)*2);
                uint32_t b0[2] = { bf0, bf2 };
                uint32_t b1[2] = { bf1, bf3 };
                mma16(s[2*pp],   a, b0);
                mma16(s[2*pp+1], a, b1);
            }
        }

        if (jt == qt) {
            const int qa = q0 + r0, qb = qa + 8;
#pragma unroll
            for (int nt = 0; nt < 8; nt++) {
                const int j = j0 + nt*8 + 2*ig;
                if (j     > qa) s[nt][0] = -1e30f;
                if (j + 1 > qa) s[nt][1] = -1e30f;
                if (j     > qb) s[nt][2] = -1e30f;
                if (j + 1 > qb) s[nt][3] = -1e30f;
            }
        }

        float a0 = -1e30f, a1 = -1e30f;
#pragma unroll
        for (int nt = 0; nt < 8; nt++) {
            a0 = fmaxf(a0, fmaxf(s[nt][0], s[nt][1]));
            a1 = fmaxf(a1, fmaxf(s[nt][2], s[nt][3]));
        }
        a0 = fmaxf(a0, __shfl_xor_sync(0xFFFFFFFFu, a0, 1));
        a0 = fmaxf(a0, __shfl_xor_sync(0xFFFFFFFFu, a0, 2));
        a1 = fmaxf(a1, __shfl_xor_sync(0xFFFFFFFFu, a1, 1));
        a1 = fmaxf(a1, __shfl_xor_sync(0xFFFFFFFFu, a1, 2));

        const float mn0 = fmaxf(m0, a0), mn1 = fmaxf(m1, a1);
        const float c0 = __expf(m0 - mn0), c1 = __expf(m1 - mn1);
        l0 *= c0; l1 *= c1;
#pragma unroll
        for (int nt = 0; nt < 8; nt++) {
            O[nt][0] *= c0; O[nt][1] *= c0;
            O[nt][2] *= c1; O[nt][3] *= c1;
        }

        float t0 = 0.f, t1 = 0.f;
#pragma unroll
        for (int nt = 0; nt < 8; nt++) {
            const float p0 = __expf(s[nt][0] - mn0);
            const float p1 = __expf(s[nt][1] - mn0);
            const float p2 = __expf(s[nt][2] - mn1);
            const float p3 = __expf(s[nt][3] - mn1);
            t0 += p0 + p1; t1 += p2 + p3;
            *(uint32_t*)(Ps + r0*AT_STR + nt*8 + 2*ig)     = pack_h2(p0, p1);
            *(uint32_t*)(Ps + (r0+8)*AT_STR + nt*8 + 2*ig) = pack_h2(p2, p3);
        }
        t0 += __shfl_xor_sync(0xFFFFFFFFu, t0, 1);
        t0 += __shfl_xor_sync(0xFFFFFFFFu, t0, 2);
        t1 += __shfl_xor_sync(0xFFFFFFFFu, t1, 1);
        t1 += __shfl_xor_sync(0xFFFFFFFFu, t1, 2);
        l0 += t0; l1 += t1;
        m0 = mn0; m1 = mn1;
        __syncwarp();

        // O += P @ V — ldmatrix a-frags + ldsm4t V b-frags
#pragma unroll
        for (int k0 = 0; k0 < 64; k0 += 16) {
            uint32_t a[4];
            ldsm4(a[0], a[1], a[2], a[3], sb_p + aoff + k0*2);
#pragma unroll
            for (int nn = 0; nn < 4; nn++) {
                uint32_t b0, b1, b2, b3;
                ldsm4t(b0, b1, b2, b3,
                       vbase + ((k0 + v_row_off)*AT_STR + nn*16 + v_col_off)*2);
                uint32_t bA[2] = { b0, b1 };
                uint32_t bB[2] = { b2, b3 };
                mma16(O[2*nn],   a, bA);
                mma16(O[2*nn+1], a, bB);
            }
        }
        __syncwarp();
    }

    const float inv0 = 1.f / l0, inv1 = 1.f / l1;
    const int b = bh >> 4, h = bh & 15;
    __half* base = g_att + ((size_t)(b*TSEQ + q0 + r0))*CDIM + h*DHEAD;
#pragma unroll
    for (int nt = 0; nt < 8; nt++) {
        *(uint32_t*)(base + nt*8 + 2*ig) =
            pack_h2(O[nt][0]*inv0, O[nt][1]*inv0);
        *(uint32_t*)(base + (size_t)8*CDIM + nt*8 + 2*ig) =
            pack_h2(O[nt][2]*inv1, O[nt][3]*inv1);
    }
}

// ---------------- launch ----------------
extern "C" void kernel_launch(void* const* d_in, const int* in_sizes, int n_in,
                              void* d_out, int out_size)
{
    (void)in_sizes; (void)n_in; (void)out_size;
    const float* x     = (const float*)d_in[0];
    const float* w_qkv = (const float*)d_in[1];
    const float* b_qkv = (const float*)d_in[2];
    const float* w_out = (const float*)d_in[3];
    const float* b_out = (const float*)d_in[4];
    float* out = (float*)d_out;

    cudaFuncSetAttribute(mm_kernel,   cudaFuncAttributeMaxDynamicSharedMemorySize, MM_SMEM);
    cudaFuncSetAttribute(attn_kernel, cudaFuncAttributeMaxDynamicSharedMemorySize, AT_SMEM);

    __half *xt, *wq, *wo;
    cudaGetSymbolAddress((void**)&xt, g_xt);
    cudaGetSymbolAddress((void**)&wq, g_wq);
    cudaGetSymbolAddress((void**)&wo, g_wo);

    // 0) one-shot fp16 conversion (x) and transpose+conversion (weights -> [N][K])
    cvtx_kernel<<<(MROWS*CDIM/4 + 255)/256, 256>>>((const float4*)x, (uint2*)xt, MROWS*CDIM/4);
    cvtw_kernel<<<dim3(3072/32, 1024/32), dim3(32, 8)>>>(w_qkv, wq, 1024, 3072);
    cvtw_kernel<<<dim3(1024/32, 1024/32), dim3(32, 8)>>>(w_out, wo, 1024, 1024);

    // 1) QKV projection + bias + head-split scatter (fp16 Q/K/V, Q pre-scaled)
    mm_kernel<<<dim3(3072/128, MROWS/128), 256, MM_SMEM>>>(xt, wq, b_qkv, nullptr, 3072, 0);
    // 2) causal flash attention (fp16, ldmatrix frags, cp.async double-buffered K/V)
    attn_kernel<<<dim3(TSEQ/64, BSZ*HH), 128, AT_SMEM>>>();
    // 3) output projection + bias (fp32 out)
    mm_kernel<<<dim3(1024/128, MROWS/128), 256, MM_SMEM>>>(nullptr, wo, b_out, out, 1024, 1);
}

// round 14
// speedup vs baseline: 1.1449x; 1.0460x over previous
#include <cuda_runtime.h>
#include <cuda_fp16.h>
#include <cstdint>

#define BSZ  4
#define TSEQ 2048
#define CDIM 1024
#define HH   16
#define DHEAD 64
#define MROWS (BSZ*TSEQ)   // 8192
#define KDIM 1024

// ---------------- device scratch (allocation-free rule), all fp16 ----------------
__device__ __align__(16) __half g_q[(size_t)BSZ*HH*TSEQ*DHEAD];
__device__ __align__(16) __half g_k[(size_t)BSZ*HH*TSEQ*DHEAD];
__device__ __align__(16) __half g_v[(size_t)BSZ*HH*TSEQ*DHEAD];
__device__ __align__(16) __half g_att[(size_t)MROWS*CDIM];
__device__ __align__(16) __half g_xt[(size_t)MROWS*CDIM];       // x, fp16
__device__ __align__(16) __half g_wq[(size_t)3*CDIM*KDIM];      // w_qkv^T [N][K] fp16
__device__ __align__(16) __half g_wo[(size_t)CDIM*KDIM];        // w_out^T [N][K] fp16

// ---------------- helpers ----------------
__device__ __forceinline__ void mma16(float* d, const uint32_t* a, const uint32_t* b) {
    asm("mma.sync.aligned.m16n8k16.row.col.f32.f16.f16.f32 "
        "{%0,%1,%2,%3}, {%4,%5,%6,%7}, {%8,%9}, {%0,%1,%2,%3};"
        : "+f"(d[0]), "+f"(d[1]), "+f"(d[2]), "+f"(d[3])
        : "r"(a[0]), "r"(a[1]), "r"(a[2]), "r"(a[3]), "r"(b[0]), "r"(b[1]));
}

__device__ __forceinline__ void ldsm4(uint32_t& r0, uint32_t& r1, uint32_t& r2, uint32_t& r3,
                                      uint32_t addr) {
    asm volatile("ldmatrix.sync.aligned.m8n8.x4.shared.b16 {%0,%1,%2,%3}, [%4];"
                 : "=r"(r0), "=r"(r1), "=r"(r2), "=r"(r3) : "r"(addr));
}

__device__ __forceinline__ void ldsm4t(uint32_t& r0, uint32_t& r1, uint32_t& r2, uint32_t& r3,
                                       uint32_t addr) {
    asm volatile("ldmatrix.sync.aligned.m8n8.x4.trans.shared.b16 {%0,%1,%2,%3}, [%4];"
                 : "=r"(r0), "=r"(r1), "=r"(r2), "=r"(r3) : "r"(addr));
}

__device__ __forceinline__ uint32_t smem_u32(const void* p) {
    uint32_t a;
    asm("{ .reg .u64 t; cvta.to.shared.u64 t, %1; cvt.u32.u64 %0, t; }" : "=r"(a) : "l"(p));
    return a;
}

__device__ __forceinline__ void cp16(uint32_t s, const void* g) {
    asm volatile("cp.async.cg.shared.global [%0], [%1], 16;" :: "r"(s), "l"(g));
}
#define CP_COMMIT() asm volatile("cp.async.commit_group;" ::: "memory")
#define CP_WAIT1()  asm volatile("cp.async.wait_group 1;" ::: "memory")
#define CP_WAIT0()  asm volatile("cp.async.wait_group 0;" ::: "memory")

__device__ __forceinline__ uint32_t pack_h2(float a, float b) {
    __half2 h = __floats2half2_rn(a, b);
    return *(uint32_t*)&h;
}

// exp2 of a packed pair computed in fp16x2 (ex2.approx.f16x2)
__device__ __forceinline__ uint32_t h2exp2_pack(float a, float b) {
    __half2 h = h2exp2(__floats2half2_rn(a, b));
    return *(uint32_t*)&h;
}

// ---------------- x: f32 -> f16 ----------------
__global__ __launch_bounds__(256)
void cvtx_kernel(const float4* __restrict__ src, uint2* __restrict__ dst, int n4)
{
    const int i = blockIdx.x * 256 + threadIdx.x;
    if (i < n4) {
        float4 v = src[i];
        dst[i] = make_uint2(pack_h2(v.x, v.y), pack_h2(v.z, v.w));
    }
}

// ---------------- weight: f32 [R][C] -> f16 transposed [C][R] ----------------
__global__ __launch_bounds__(256)
void cvtw_kernel(const float* __restrict__ src, __half* __restrict__ dst, int R, int C)
{
    __shared__ float t[32][33];
    const int c0 = blockIdx.x * 32, r0 = blockIdx.y * 32;
    const int tx = threadIdx.x, ty = threadIdx.y;
#pragma unroll
    for (int i = 0; i < 4; i++)
        t[ty + 8*i][tx] = src[(size_t)(r0 + ty + 8*i) * C + c0 + tx];
    __syncthreads();
#pragma unroll
    for (int i = 0; i < 4; i++)
        dst[(size_t)(c0 + ty + 8*i) * R + r0 + tx] = __float2half_rn(t[tx][ty + 8*i]);
}

// ---------------- fp16 mma.sync GEMM (unchanged R13: CTA 128x128, BK=64, 2 CTA/SM) ----------------
#define BK 64
#define MA_STR 72
#define MA_H (128*MA_STR)               // 9216 halves per tile
#define ST_H (2*MA_H)                   // 18432 halves = 36864 B
#define STAGES 3
#define MM_SMEM (STAGES*ST_H*2)         // 110592 B

__global__ __launch_bounds__(256, 2)
void mm_kernel(const __half* __restrict__ A, const __half* __restrict__ Bt,
               const float* __restrict__ bias, float* __restrict__ Cout,
               int N, int mode)
{
    extern __shared__ __half smh[];
    const uint32_t sb = smem_u32(smh);

    const int tid  = threadIdx.x;
    const int lane = tid & 31;
    const int warp = tid >> 5;
    const int wm = (warp >> 2) * 64;
    const int wn = (warp & 3) * 32;
    const int g  = lane >> 2;
    const int ig = lane & 3;

    const int m0 = blockIdx.y * 128;
    const int n0 = blockIdx.x * 128;

    if (mode) A = g_att;

    const uint32_t aoff = ((wm + (lane & 15)) * MA_STR + (lane >> 4) * 8) * 2;
    const uint32_t boff = ((wn + (lane & 15)) * MA_STR + (lane >> 4) * 8) * 2;

    float d[4][4][4];
#pragma unroll
    for (int mt = 0; mt < 4; mt++)
#pragma unroll
        for (int nt = 0; nt < 4; nt++)
#pragma unroll
            for (int r = 0; r < 4; r++) d[mt][nt][r] = 0.f;

#define LDG_ASYNC(c, st) do {                                                     \
    uint32_t _sa = sb + (st)*ST_H*2;                                              \
    uint32_t _sb2 = _sa + MA_H*2;                                                 \
    _Pragma("unroll") for (int i = 0; i < 4; i++) {                               \
        int idx = tid + 256*i; int row = idx >> 3, c8 = idx & 7;                  \
        cp16(_sa + (row*MA_STR + c8*8)*2,                                         \
             A + (size_t)(m0 + row)*KDIM + (c)*BK + c8*8); }                      \
    _Pragma("unroll") for (int i = 0; i < 4; i++) {                               \
        int idx = tid + 256*i; int row = idx >> 3, c8 = idx & 7;                  \
        cp16(_sb2 + (row*MA_STR + c8*8)*2,                                        \
             Bt + (size_t)(n0 + row)*KDIM + (c)*BK + c8*8); }                     \
} while (0)

#define COMPUTE(st) do {                                                          \
    const uint32_t _ab = sb + (st)*ST_H*2 + aoff;                                 \
    const uint32_t _bb = sb + (st)*ST_H*2 + MA_H*2 + boff;                        \
    _Pragma("unroll") for (int s = 0; s < 4; s++) {                               \
        const int k0 = s*16;                                                      \
        uint32_t af[4][4], bf[2][4];                                              \
        _Pragma("unroll") for (int mt = 0; mt < 4; mt++)                          \
            ldsm4(af[mt][0], af[mt][1], af[mt][2], af[mt][3],                     \
                  _ab + (mt*16*MA_STR + k0)*2);                                   \
        _Pragma("unroll") for (int p = 0; p < 2; p++)                             \
            ldsm4(bf[p][0], bf[p][1], bf[p][2], bf[p][3],                         \
                  _bb + (p*16*MA_STR + k0)*2);                                    \
        _Pragma("unroll") for (int mt = 0; mt < 4; mt++)                          \
            _Pragma("unroll") for (int p = 0; p < 2; p++) {                       \
                uint32_t b0[2] = { bf[p][0], bf[p][2] };                          \
                uint32_t b1[2] = { bf[p][1], bf[p][3] };                          \
                mma16(d[mt][2*p],   af[mt], b0);                                  \
                mma16(d[mt][2*p+1], af[mt], b1);                                  \
            }                                                                     \
    }                                                                             \
} while (0)

    LDG_ASYNC(0, 0); CP_COMMIT();
    LDG_ASYNC(1, 1); CP_COMMIT();

#pragma unroll 1
    for (int c = 0; c < KDIM/BK; c++) {
        CP_WAIT1();
        __syncthreads();
        if (c + 2 < KDIM/BK) {
            const int st = (c + 2) % STAGES;
            LDG_ASYNC(c + 2, st);
        }
        CP_COMMIT();
        COMPUTE(c % STAGES);
    }

#pragma unroll
    for (int mt = 0; mt < 4; mt++) {
        const int r0 = m0 + wm + mt*16 + g;
#pragma unroll
        for (int nt = 0; nt < 4; nt++) {
            const int c0 = n0 + wn + nt*8 + ig*2;
            const float b0 = bias[c0], b1 = bias[c0+1];
            if (mode == 0) {
                const int sec = c0 >> 10;
                const int h   = (c0 & 1023) >> 6;
                const int dd  = c0 & 63;
                __half* dstp = (sec == 0) ? g_q : ((sec == 1) ? g_k : g_v);
                // Q pre-scale folds 1/sqrt(Dh) AND log2(e) (attention works in 2^x domain)
                const float scale = (sec == 0) ? 0.125f * 1.44269504f : 1.0f;
#pragma unroll
                for (int rr = 0; rr < 2; rr++) {
                    const int r = r0 + rr*8;
                    const int b = r >> 11, t = r & 2047;
                    uint32_t v = pack_h2((d[mt][nt][rr*2+0] + b0) * scale,
                                         (d[mt][nt][rr*2+1] + b1) * scale);
                    *(uint32_t*)(dstp + (((size_t)(b*HH + h))*TSEQ + t)*DHEAD + dd) = v;
                }
            } else {
#pragma unroll
                for (int rr = 0; rr < 2; rr++) {
                    const int r = r0 + rr*8;
                    float2 v = make_float2(d[mt][nt][rr*2+0] + b0, d[mt][nt][rr*2+1] + b1);
                    *(float2*)(Cout + (size_t)r*N + c0) = v;
                }
            }
        }
    }
}

// ---------------- fp16 flash attention: register P-pass + h2exp2 + ones-MMA l ----------------
// smem: Q + 2K + 2V only (no P buffer) = 46080 B -> 4 CTA/SM (16 warps).
#define AT_STR 72
#define T_H (64*AT_STR)                 // 4608 halves = 9216 B per tile
#define AT_SMEM ((5*T_H)*2)             // 46080 B

__global__ __launch_bounds__(128, 4)
void attn_kernel()
{
    extern __shared__ __half smh[];
    __half* Qs  = smh;
    __half* Kst = Qs + T_H;              // 2 stages
    __half* Vst = Kst + 2*T_H;           // 2 stages
    const uint32_t sb_q = smem_u32(Qs);
    const uint32_t sb_k = smem_u32(Kst);
    const uint32_t sb_v = smem_u32(Vst);

    const int tid  = threadIdx.x;
    const int lane = tid & 31;
    const int w    = tid >> 5;
    const int g    = lane >> 2;
    const int ig   = lane & 3;
    const int bh = blockIdx.y;
    const int qt = (gridDim.x - 1) - blockIdx.x;   // long blocks first
    const int q0 = qt * 64;

    const __half* Qg = g_q + (size_t)bh * TSEQ * DHEAD;
    const __half* Kg = g_k + (size_t)bh * TSEQ * DHEAD;
    const __half* Vg = g_v + (size_t)bh * TSEQ * DHEAD;

    const uint32_t aoff = ((16*w + (lane & 15)) * AT_STR + (lane >> 4) * 8) * 2;
    const uint32_t koff = (((lane & 15)) * AT_STR + (lane >> 4) * 8) * 2;

#define PREFETCH_KV(j0, st) do {                                                  \
    uint32_t _kb = sb_k + (st)*T_H*2;                                             \
    uint32_t _vb = sb_v + (st)*T_H*2;                                             \
    _Pragma("unroll") for (int i = 0; i < 4; i++) {                               \
        int f = tid + 128*i; int row = f >> 3, c8 = f & 7;                        \
        cp16(_kb + (row*AT_STR + c8*8)*2, Kg + (size_t)((j0)+row)*DHEAD + c8*8);  \
        cp16(_vb + (row*AT_STR + c8*8)*2, Vg + (size_t)((j0)+row)*DHEAD + c8*8);  \
    }                                                                             \
} while (0)

    // Q tile: raw copy (already scaled fp16, log2 domain)
#pragma unroll
    for (int i = 0; i < 4; i++) {
        const int f = tid + 128*i;
        const int row = f >> 3, c8 = f & 7;
        *(uint4*)(Qs + row*AT_STR + c8*8) =
            *(const uint4*)(Qg + (size_t)(q0+row)*DHEAD + c8*8);
    }

    PREFETCH_KV(0, 0);
    CP_COMMIT();

    const int r0 = 16*w + g;
    float O[8][4];
#pragma unroll
    for (int nt = 0; nt < 8; nt++)
#pragma unroll
        for (int r = 0; r < 4; r++) O[nt][r] = 0.f;
    float Ol[4] = {0.f, 0.f, 0.f, 0.f};     // l accumulated via ones-MMA
    float m0 = -1e30f, m1 = -1e30f;

    const int mi  = lane >> 3;
    const int rin = lane & 7;
    const int v_row_off = ((mi & 1) ? 8 : 0) + rin;
    const int v_col_off = (mi >> 1) ? 8 : 0;

    const uint32_t ones2[2] = { 0x3C003C00u, 0x3C003C00u };   // fp16 (1,1)

#pragma unroll 1
    for (int jt = 0; jt <= qt; jt++) {
        const int j0 = jt * 64;
        const int p = jt & 1;

        CP_WAIT0();
        __syncthreads();

        if (jt < qt) {
            PREFETCH_KV(j0 + 64, p ^ 1);
            CP_COMMIT();
        }

        const uint32_t kbase = sb_k + p*T_H*2 + koff;
        const uint32_t vbase = sb_v + p*T_H*2;

        // S = Q K^T  (16x64 per warp) — ldmatrix frags; s is in log2 scale
        float s[8][4];
#pragma unroll
        for (int nt = 0; nt < 8; nt++)
#pragma unroll
            for (int r = 0; r < 4; r++) s[nt][r] = 0.f;

#pragma unroll
        for (int k0 = 0; k0 < 64; k0 += 16) {
            uint32_t a[4];
            ldsm4(a[0], a[1], a[2], a[3], sb_q + aoff + k0*2);
#pragma unroll
            for (int pp = 0; pp < 4; pp++) {
                uint32_t bf0, bf1, bf2, bf3;
                ldsm4(bf0, bf1, bf2, bf3, kbase + (pp*16*AT_STR + k0)*2);
                uint32_t b0[2] = { bf0, bf2 };
                uint32_t b1[2] = { bf1, bf3 };
                mma16(s[2*pp],   a, b0);
                mma16(s[2*pp+1], a, b1);
            }
        }

        if (jt == qt) {
            const int qa = q0 + r0, qb = qa + 8;
#pragma unroll
            for (int nt = 0; nt < 8; nt++) {
                const int j = j0 + nt*8 + 2*ig;
                if (j     > qa) s[nt][0] = -1e30f;
                if (j + 1 > qa) s[nt][1] = -1e30f;
                if (j     > qb) s[nt][2] = -1e30f;
                if (j + 1 > qb) s[nt][3] = -1e30f;
            }
        }

        float a0 = -1e30f, a1 = -1e30f;
#pragma unroll
        for (int nt = 0; nt < 8; nt++) {
            a0 = fmaxf(a0, fmaxf(s[nt][0], s[nt][1]));
            a1 = fmaxf(a1, fmaxf(s[nt][2], s[nt][3]));
        }
        a0 = fmaxf(a0, __shfl_xor_sync(0xFFFFFFFFu, a0, 1));
        a0 = fmaxf(a0, __shfl_xor_sync(0xFFFFFFFFu, a0, 2));
        a1 = fmaxf(a1, __shfl_xor_sync(0xFFFFFFFFu, a1, 1));
        a1 = fmaxf(a1, __shfl_xor_sync(0xFFFFFFFFu, a1, 2));

        const float mn0 = fmaxf(m0, a0), mn1 = fmaxf(m1, a1);
        const float c0 = exp2f(m0 - mn0), c1 = exp2f(m1 - mn1);
#pragma unroll
        for (int nt = 0; nt < 8; nt++) {
            O[nt][0] *= c0; O[nt][1] *= c0;
            O[nt][2] *= c1; O[nt][3] *= c1;
        }
        Ol[0] *= c0; Ol[1] *= c0; Ol[2] *= c1; Ol[3] *= c1;

        // P = 2^(s - mn) computed directly into A-fragment registers (fp16x2 ex2)
        uint32_t pa_lo[8], pa_hi[8];
#pragma unroll
        for (int nt = 0; nt < 8; nt++) {
            pa_lo[nt] = h2exp2_pack(s[nt][0] - mn0, s[nt][1] - mn0);
            pa_hi[nt] = h2exp2_pack(s[nt][2] - mn1, s[nt][3] - mn1);
        }
        m0 = mn0; m1 = mn1;

        // O += P @ V  (a-frags from registers; V b-frags via ldsm4t; l via ones-MMA)
#pragma unroll
        for (int ks = 0; ks < 4; ks++) {
            const int k0 = ks*16;
            uint32_t a[4] = { pa_lo[2*ks], pa_hi[2*ks], pa_lo[2*ks+1], pa_hi[2*ks+1] };
            mma16(Ol, a, ones2);
#pragma unroll
            for (int nn = 0; nn < 4; nn++) {
                uint32_t b0, b1, b2, b3;
                ldsm4t(b0, b1, b2, b3,
                       vbase + ((k0 + v_row_off)*AT_STR + nn*16 + v_col_off)*2);
                uint32_t bA[2] = { b0, b1 };
                uint32_t bB[2] = { b2, b3 };
                mma16(O[2*nn],   a, bA);
                mma16(O[2*nn+1], a, bB);
            }
        }
    }

    // normalize (l = Ol row sums), write g_att as fp16
    const float inv0 = 1.f / Ol[0], inv1 = 1.f / Ol[2];
    const int b = bh >> 4, h = bh & 15;
    __half* base = g_att + ((size_t)(b*TSEQ + q0 + r0))*CDIM + h*DHEAD;
#pragma unroll
    for (int nt = 0; nt < 8; nt++) {
        *(uint32_t*)(base + nt*8 + 2*ig) =
            pack_h2(O[nt][0]*inv0, O[nt][1]*inv0);
        *(uint32_t*)(base + (size_t)8*CDIM + nt*8 + 2*ig) =
            pack_h2(O[nt][2]*inv1, O[nt][3]*inv1);
    }
}

// ---------------- launch ----------------
extern "C" void kernel_launch(void* const* d_in, const int* in_sizes, int n_in,
                              void* d_out, int out_size)
{
    (void)in_sizes; (void)n_in; (void)out_size;
    const float* x     = (const float*)d_in[0];
    const float* w_qkv = (const float*)d_in[1];
    const float* b_qkv = (const float*)d_in[2];
    const float* w_out = (const float*)d_in[3];
    const float* b_out = (const float*)d_in[4];
    float* out = (float*)d_out;

    cudaFuncSetAttribute(mm_kernel,   cudaFuncAttributeMaxDynamicSharedMemorySize, MM_SMEM);
    cudaFuncSetAttribute(attn_kernel, cudaFuncAttributeMaxDynamicSharedMemorySize, AT_SMEM);

    __half *xt, *wq, *wo;
    cudaGetSymbolAddress((void**)&xt, g_xt);
    cudaGetSymbolAddress((void**)&wq, g_wq);
    cudaGetSymbolAddress((void**)&wo, g_wo);

    // 0) one-shot fp16 conversion (x) and transpose+conversion (weights -> [N][K])
    cvtx_kernel<<<(MROWS*CDIM/4 + 255)/256, 256>>>((const float4*)x, (uint2*)xt, MROWS*CDIM/4);
    cvtw_kernel<<<dim3(3072/32, 1024/32), dim3(32, 8)>>>(w_qkv, wq, 1024, 3072);
    cvtw_kernel<<<dim3(1024/32, 1024/32), dim3(32, 8)>>>(w_out, wo, 1024, 1024);

    // 1) QKV projection + bias + head-split scatter (fp16 Q/K/V, Q pre-scaled incl. log2e)
    mm_kernel<<<dim3(3072/128, MROWS/128), 256, MM_SMEM>>>(xt, wq, b_qkv, nullptr, 3072, 0);
    // 2) causal flash attention (fp16, register P-pass, ones-MMA l, h2exp2)
    attn_kernel<<<dim3(TSEQ/64, BSZ*HH), 128, AT_SMEM>>>();
    // 3) output projection + bias (fp32 out)
    mm_kernel<<<dim3(1024/128, MROWS/128), 256, MM_SMEM>>>(nullptr, wo, b_out, out, 1024, 1);
}

// round 16
// speedup vs baseline: 1.2173x; 1.0632x over previous
#include <cuda_runtime.h>
#include <cuda_fp16.h>
#include <cstdint>

#define BSZ  4
#define TSEQ 2048
#define CDIM 1024
#define HH   16
#define DHEAD 64
#define MROWS (BSZ*TSEQ)   // 8192
#define KDIM 1024

// ---------------- device scratch (allocation-free rule), all fp16 ----------------
__device__ __align__(16) __half g_q[(size_t)BSZ*HH*TSEQ*DHEAD];
__device__ __align__(16) __half g_k[(size_t)BSZ*HH*TSEQ*DHEAD];
__device__ __align__(16) __half g_v[(size_t)BSZ*HH*TSEQ*DHEAD];
__device__ __align__(16) __half g_att[(size_t)MROWS*CDIM];
__device__ __align__(16) __half g_xt[(size_t)MROWS*CDIM];       // x, fp16
__device__ __align__(16) __half g_wq[(size_t)3*CDIM*KDIM];      // w_qkv^T [N][K] fp16
__device__ __align__(16) __half g_wo[(size_t)CDIM*KDIM];        // w_out^T [N][K] fp16

// ---------------- helpers ----------------
__device__ __forceinline__ void mma16(float* d, const uint32_t* a, const uint32_t* b) {
    asm("mma.sync.aligned.m16n8k16.row.col.f32.f16.f16.f32 "
        "{%0,%1,%2,%3}, {%4,%5,%6,%7}, {%8,%9}, {%0,%1,%2,%3};"
        : "+f"(d[0]), "+f"(d[1]), "+f"(d[2]), "+f"(d[3])
        : "r"(a[0]), "r"(a[1]), "r"(a[2]), "r"(a[3]), "r"(b[0]), "r"(b[1]));
}

__device__ __forceinline__ void ldsm4(uint32_t& r0, uint32_t& r1, uint32_t& r2, uint32_t& r3,
                                      uint32_t addr) {
    asm volatile("ldmatrix.sync.aligned.m8n8.x4.shared.b16 {%0,%1,%2,%3}, [%4];"
                 : "=r"(r0), "=r"(r1), "=r"(r2), "=r"(r3) : "r"(addr));
}

__device__ __forceinline__ void ldsm4t(uint32_t& r0, uint32_t& r1, uint32_t& r2, uint32_t& r3,
                                       uint32_t addr) {
    asm volatile("ldmatrix.sync.aligned.m8n8.x4.trans.shared.b16 {%0,%1,%2,%3}, [%4];"
                 : "=r"(r0), "=r"(r1), "=r"(r2), "=r"(r3) : "r"(addr));
}

__device__ __forceinline__ uint32_t smem_u32(const void* p) {
    uint32_t a;
    asm("{ .reg .u64 t; cvta.to.shared.u64 t, %1; cvt.u32.u64 %0, t; }" : "=r"(a) : "l"(p));
    return a;
}

__device__ __forceinline__ void cp16(uint32_t s, const void* g) {
    asm volatile("cp.async.cg.shared.global [%0], [%1], 16;" :: "r"(s), "l"(g));
}
#define CP_COMMIT() asm volatile("cp.async.commit_group;" ::: "memory")
#define CP_WAIT0()  asm volatile("cp.async.wait_group 0;" ::: "memory")

// ---- mbarrier primitives (sm_80-class; no tcgen05) ----
#define MBAR_INIT(addr, cnt) \
    asm volatile("mbarrier.init.shared.b64 [%0], %1;" :: "r"((uint32_t)(addr)), "r"((uint32_t)(cnt)) : "memory")
#define MBAR_ARRIVE(addr) \
    asm volatile("mbarrier.arrive.shared.b64 _, [%0];" :: "r"((uint32_t)(addr)) : "memory")
// NOINC is load-bearing: default cp.async.mbarrier.arrive increments the pending
// count (net-zero vs the fixed 256 expected arrivals) and deadlocks the barrier.
#define CPASYNC_MBAR_ARRIVE(addr) \
    asm volatile("cp.async.mbarrier.arrive.noinc.shared.b64 [%0];" :: "r"((uint32_t)(addr)) : "memory")
#define MBAR_WAIT(addr, parity) do {                                              \
    uint32_t _m = (uint32_t)(addr); uint32_t _p = (uint32_t)(parity);             \
    asm volatile(                                                                 \
        "{\n\t.reg .pred P1;\n\t"                                                 \
        "WL_%=:\n\t"                                                              \
        "mbarrier.try_wait.parity.acquire.cta.shared::cta.b64 P1, [%0], %1, 0x989680;\n\t" \
        "@P1 bra.uni WD_%=;\n\t"                                                  \
        "bra.uni WL_%=;\n\t"                                                      \
        "WD_%=:\n\t}"                                                             \
        :: "r"(_m), "r"(_p) : "memory");                                          \
} while (0)

__device__ __forceinline__ uint32_t pack_h2(float a, float b) {
    __half2 h = __floats2half2_rn(a, b);
    return *(uint32_t*)&h;
}

__device__ __forceinline__ uint32_t h2exp2_pack(float a, float b) {
    __half2 h = h2exp2(__floats2half2_rn(a, b));
    return *(uint32_t*)&h;
}

// ---------------- x: f32 -> f16 ----------------
__global__ __launch_bounds__(256)
void cvtx_kernel(const float4* __restrict__ src, uint2* __restrict__ dst, int n4)
{
    const int i = blockIdx.x * 256 + threadIdx.x;
    if (i < n4) {
        float4 v = src[i];
        dst[i] = make_uint2(pack_h2(v.x, v.y), pack_h2(v.z, v.w));
    }
}

// ---------------- weight: f32 [R][C] -> f16 transposed [C][R] ----------------
__global__ __launch_bounds__(256)
void cvtw_kernel(const float* __restrict__ src, __half* __restrict__ dst, int R, int C)
{
    __shared__ float t[32][33];
    const int c0 = blockIdx.x * 32, r0 = blockIdx.y * 32;
    const int tx = threadIdx.x, ty = threadIdx.y;
#pragma unroll
    for (int i = 0; i < 4; i++)
        t[ty + 8*i][tx] = src[(size_t)(r0 + ty + 8*i) * C + c0 + tx];
    __syncthreads();
#pragma unroll
    for (int i = 0; i < 4; i++)
        dst[(size_t)(c0 + ty + 8*i) * R + r0 + tx] = __float2half_rn(t[tx][ty + 8*i]);
}

// ---------------- fp16 mma.sync GEMM: mbarrier-phased 3-stage pipeline ----------------
// CTA 128x128, BK=64, 256 thr = 8 warps (2m x 4n), 2 CTA/SM.
// Smem: [128B mbarrier header][3 stages of (A|B) tiles, stride-72 rows].
#define BK 64
#define MA_STR 72
#define MA_H (128*MA_STR)               // 9216 halves per tile
#define ST_H (2*MA_H)                   // 18432 halves = 36864 B
#define STAGES 3
#define HDR_H 64                        // 128 B header (6 mbarriers)
#define MM_SMEM ((HDR_H + STAGES*ST_H)*2)   // 110720 B

__global__ __launch_bounds__(256, 2)
void mm_kernel(const __half* __restrict__ A, const __half* __restrict__ Bt,
               const float* __restrict__ bias, float* __restrict__ Cout,
               int N, int mode)
{
    extern __shared__ __half smh[];
    const uint32_t sb  = smem_u32(smh);          // mbarrier header base
    const uint32_t sd  = sb + HDR_H*2;           // stage data base (bytes)

    const int tid  = threadIdx.x;
    const int lane = tid & 31;
    const int warp = tid >> 5;
    const int wm = (warp >> 2) * 64;
    const int wn = (warp & 3) * 32;
    const int g  = lane >> 2;
    const int ig = lane & 3;

    const int m0 = blockIdx.y * 128;
    const int n0 = blockIdx.x * 128;

    if (mode) A = g_att;

    const uint32_t aoff = ((wm + (lane & 15)) * MA_STR + (lane >> 4) * 8) * 2;
    const uint32_t boff = ((wn + (lane & 15)) * MA_STR + (lane >> 4) * 8) * 2;

    // full[s] at sb + s*16, empty[s] at sb + s*16 + 8
    if (tid == 0) {
#pragma unroll
        for (int s = 0; s < STAGES; s++) {
            MBAR_INIT(sb + s*16,     256);
            MBAR_INIT(sb + s*16 + 8, 256);
        }
    }
    __syncthreads();

    float d[4][4][4];
#pragma unroll
    for (int mt = 0; mt < 4; mt++)
#pragma unroll
        for (int nt = 0; nt < 4; nt++)
#pragma unroll
            for (int r = 0; r < 4; r++) d[mt][nt][r] = 0.f;

#define LDG_ASYNC(c, st) do {                                                     \
    uint32_t _sa = sd + (st)*ST_H*2;                                              \
    uint32_t _sb2 = _sa + MA_H*2;                                                 \
    _Pragma("unroll") for (int i = 0; i < 4; i++) {                               \
        int idx = tid + 256*i; int row = idx >> 3, c8 = idx & 7;                  \
        cp16(_sa + (row*MA_STR + c8*8)*2,                                         \
             A + (size_t)(m0 + row)*KDIM + (c)*BK + c8*8); }                      \
    _Pragma("unroll") for (int i = 0; i < 4; i++) {                               \
        int idx = tid + 256*i; int row = idx >> 3, c8 = idx & 7;                  \
        cp16(_sb2 + (row*MA_STR + c8*8)*2,                                        \
             Bt + (size_t)(n0 + row)*KDIM + (c)*BK + c8*8); }                     \
} while (0)

#define COMPUTE(st) do {                                                          \
    const uint32_t _ab = sd + (st)*ST_H*2 + aoff;                                 \
    const uint32_t _bb = sd + (st)*ST_H*2 + MA_H*2 + boff;                        \
    _Pragma("unroll") for (int s = 0; s < 4; s++) {                               \
        const int k0 = s*16;                                                      \
        uint32_t af[4][4], bf[2][4];                                              \
        _Pragma("unroll") for (int mt = 0; mt < 4; mt++)                          \
            ldsm4(af[mt][0], af[mt][1], af[mt][2], af[mt][3],                     \
                  _ab + (mt*16*MA_STR + k0)*2);                                   \
        _Pragma("unroll") for (int p = 0; p < 2; p++)                             \
            ldsm4(bf[p][0], bf[p][1], bf[p][2], bf[p][3],                         \
                  _bb + (p*16*MA_STR + k0)*2);                                    \
        _Pragma("unroll") for (int mt = 0; mt < 4; mt++)                          \
            _Pragma("unroll") for (int p = 0; p < 2; p++) {                       \
                uint32_t b0[2] = { bf[p][0], bf[p][2] };                          \
                uint32_t b1[2] = { bf[p][1], bf[p][3] };                          \
                mma16(d[mt][2*p],   af[mt], b0);                                  \
                mma16(d[mt][2*p+1], af[mt], b1);                                  \
            }                                                                     \
    }                                                                             \
} while (0)

    // prefill chunks 0,1 (empty barriers fresh -> no wait needed)
    LDG_ASYNC(0, 0); CPASYNC_MBAR_ARRIVE(sb + 0*16);
    LDG_ASYNC(1, 1); CPASYNC_MBAR_ARRIVE(sb + 1*16);

#pragma unroll 1
    for (int c = 0; c < KDIM/BK; c++) {
        const int st = c % STAGES;
        MBAR_WAIT(sb + st*16, (c/STAGES) & 1);          // data ready
        if (c + 2 < KDIM/BK) {
            const int m = c + 2, st2 = m % STAGES;
            MBAR_WAIT(sb + st2*16 + 8, ((m/STAGES) & 1) ^ 1);   // stage free
            LDG_ASYNC(m, st2);
            CPASYNC_MBAR_ARRIVE(sb + st2*16);
        }
        COMPUTE(st);
        MBAR_ARRIVE(sb + st*16 + 8);                    // done reading stage
    }

#pragma unroll
    for (int mt = 0; mt < 4; mt++) {
        const int r0 = m0 + wm + mt*16 + g;
#pragma unroll
        for (int nt = 0; nt < 4; nt++) {
            const int c0 = n0 + wn + nt*8 + ig*2;
            const float b0 = bias[c0], b1 = bias[c0+1];
            if (mode == 0) {
                const int sec = c0 >> 10;
                const int h   = (c0 & 1023) >> 6;
                const int dd  = c0 & 63;
                __half* dstp = (sec == 0) ? g_q : ((sec == 1) ? g_k : g_v);
                // Q pre-scale folds 1/sqrt(Dh) AND log2(e) (attention works in 2^x domain)
                const float scale = (sec == 0) ? 0.125f * 1.44269504f : 1.0f;
#pragma unroll
                for (int rr = 0; rr < 2; rr++) {
                    const int r = r0 + rr*8;
                    const int b = r >> 11, t = r & 2047;
                    uint32_t v = pack_h2((d[mt][nt][rr*2+0] + b0) * scale,
                                         (d[mt][nt][rr*2+1] + b1) * scale);
                    *(uint32_t*)(dstp + (((size_t)(b*HH + h))*TSEQ + t)*DHEAD + dd) = v;
                }
            } else {
#pragma unroll
                for (int rr = 0; rr < 2; rr++) {
                    const int r = r0 + rr*8;
                    float2 v = make_float2(d[mt][nt][rr*2+0] + b0, d[mt][nt][rr*2+1] + b1);
                    *(float2*)(Cout + (size_t)r*N + c0) = v;
                }
            }
        }
    }
}

// ---------------- fp16 flash attention (unchanged R14): register P-pass + h2exp2 + ones-MMA l ----------------
#define AT_STR 72
#define T_H (64*AT_STR)                 // 4608 halves = 9216 B per tile
#define AT_SMEM ((5*T_H)*2)             // 46080 B

__global__ __launch_bounds__(128, 4)
void attn_kernel()
{
    extern __shared__ __half smh[];
    __half* Qs  = smh;
    __half* Kst = Qs + T_H;              // 2 stages
    __half* Vst = Kst + 2*T_H;           // 2 stages
    const uint32_t sb_q = smem_u32(Qs);
    const uint32_t sb_k = smem_u32(Kst);
    const uint32_t sb_v = smem_u32(Vst);

    const int tid  = threadIdx.x;
    const int lane = tid & 31;
    const int w    = tid >> 5;
    const int g    = lane >> 2;
    const int ig   = lane & 3;
    const int bh = blockIdx.y;
    const int qt = (gridDim.x - 1) - blockIdx.x;   // long blocks first
    const int q0 = qt * 64;

    const __half* Qg = g_q + (size_t)bh * TSEQ * DHEAD;
    const __half* Kg = g_k + (size_t)bh * TSEQ * DHEAD;
    const __half* Vg = g_v + (size_t)bh * TSEQ * DHEAD;

    const uint32_t aoff = ((16*w + (lane & 15)) * AT_STR + (lane >> 4) * 8) * 2;
    const uint32_t koff = (((lane & 15)) * AT_STR + (lane >> 4) * 8) * 2;

#define PREFETCH_KV(j0, st) do {                                                  \
    uint32_t _kb = sb_k + (st)*T_H*2;                                             \
    uint32_t _vb = sb_v + (st)*T_H*2;                                             \
    _Pragma("unroll") for (int i = 0; i < 4; i++) {                               \
        int f = tid + 128*i; int row = f >> 3, c8 = f & 7;                        \
        cp16(_kb + (row*AT_STR + c8*8)*2, Kg + (size_t)((j0)+row)*DHEAD + c8*8);  \
        cp16(_vb + (row*AT_STR + c8*8)*2, Vg + (size_t)((j0)+row)*DHEAD + c8*8);  \
    }                                                                             \
} while (0)

    // Q tile: raw copy (already scaled fp16, log2 domain)
#pragma unroll
    for (int i = 0; i < 4; i++) {
        const int f = tid + 128*i;
        const int row = f >> 3, c8 = f & 7;
        *(uint4*)(Qs + row*AT_STR + c8*8) =
            *(const uint4*)(Qg + (size_t)(q0+row)*DHEAD + c8*8);
    }

    PREFETCH_KV(0, 0);
    CP_COMMIT();

    const int r0 = 16*w + g;
    float O[8][4];
#pragma unroll
    for (int nt = 0; nt < 8; nt++)
#pragma unroll
        for (int r = 0; r < 4; r++) O[nt][r] = 0.f;
    float Ol[4] = {0.f, 0.f, 0.f, 0.f};
    float m0 = -1e30f, m1 = -1e30f;

    const int mi  = lane >> 3;
    const int rin = lane & 7;
    const int v_row_off = ((mi & 1) ? 8 : 0) + rin;
    const int v_col_off = (mi >> 1) ? 8 : 0;

    const uint32_t ones2[2] = { 0x3C003C00u, 0x3C003C00u };   // fp16 (1,1)

#pragma unroll 1
    for (int jt = 0; jt <= qt; jt++) {
        const int j0 = jt * 64;
        const int p = jt & 1;

        CP_WAIT0();
        __syncthreads();

        if (jt < qt) {
            PREFETCH_KV(j0 + 64, p ^ 1);
            CP_COMMIT();
        }

        const uint32_t kbase = sb_k + p*T_H*2 + koff;
        const uint32_t vbase = sb_v + p*T_H*2;

        float s[8][4];
#pragma unroll
        for (int nt = 0; nt < 8; nt++)
#pragma unroll
            for (int r = 0; r < 4; r++) s[nt][r] = 0.f;

#pragma unroll
        for (int k0 = 0; k0 < 64; k0 += 16) {
            uint32_t a[4];
            ldsm4(a[0], a[1], a[2], a[3], sb_q + aoff + k0*2);
#pragma unroll
            for (int pp = 0; pp < 4; pp++) {
                uint32_t bf0, bf1, bf2, bf3;
                ldsm4(bf0, bf1, bf2, bf3, kbase + (pp*16*AT_STR + k0)*2);
                uint32_t b0[2] = { bf0, bf2 };
                uint32_t b1[2] = { bf1, bf3 };
                mma16(s[2*pp],   a, b0);
                mma16(s[2*pp+1], a, b1);
            }
        }

        if (jt == qt) {
            const int qa = q0 + r0, qb = qa + 8;
#pragma unroll
            for (int nt = 0; nt < 8; nt++) {
                const int j = j0 + nt*8 + 2*ig;
                if (j     > qa) s[nt][0] = -1e30f;
                if (j + 1 > qa) s[nt][1] = -1e30f;
                if (j     > qb) s[nt][2] = -1e30f;
                if (j + 1 > qb) s[nt][3] = -1e30f;
            }
        }

        float a0 = -1e30f, a1 = -1e30f;
#pragma unroll
        for (int nt = 0; nt < 8; nt++) {
            a0 = fmaxf(a0, fmaxf(s[nt][0], s[nt][1]));
            a1 = fmaxf(a1, fmaxf(s[nt][2], s[nt][3]));
        }
        a0 = fmaxf(a0, __shfl_xor_sync(0xFFFFFFFFu, a0, 1));
        a0 = fmaxf(a0, __shfl_xor_sync(0xFFFFFFFFu, a0, 2));
        a1 = fmaxf(a1, __shfl_xor_sync(0xFFFFFFFFu, a1, 1));
        a1 = fmaxf(a1, __shfl_xor_sync(0xFFFFFFFFu, a1, 2));

        const float mn0 = fmaxf(m0, a0), mn1 = fmaxf(m1, a1);
        const float c0 = exp2f(m0 - mn0), c1 = exp2f(m1 - mn1);
#pragma unroll
        for (int nt = 0; nt < 8; nt++) {
            O[nt][0] *= c0; O[nt][1] *= c0;
            O[nt][2] *= c1; O[nt][3] *= c1;
        }
        Ol[0] *= c0; Ol[1] *= c0; Ol[2] *= c1; Ol[3] *= c1;

        uint32_t pa_lo[8], pa_hi[8];
#pragma unroll
        for (int nt = 0; nt < 8; nt++) {
            pa_lo[nt] = h2exp2_pack(s[nt][0] - mn0, s[nt][1] - mn0);
            pa_hi[nt] = h2exp2_pack(s[nt][2] - mn1, s[nt][3] - mn1);
        }
        m0 = mn0; m1 = mn1;

#pragma unroll
        for (int ks = 0; ks < 4; ks++) {
            const int k0 = ks*16;
            uint32_t a[4] = { pa_lo[2*ks], pa_hi[2*ks], pa_lo[2*ks+1], pa_hi[2*ks+1] };
            mma16(Ol, a, ones2);
#pragma unroll
            for (int nn = 0; nn < 4; nn++) {
                uint32_t b0, b1, b2, b3;
                ldsm4t(b0, b1, b2, b3,
                       vbase + ((k0 + v_row_off)*AT_STR + nn*16 + v_col_off)*2);
                uint32_t bA[2] = { b0, b1 };
                uint32_t bB[2] = { b2, b3 };
                mma16(O[2*nn],   a, bA);
                mma16(O[2*nn+1], a, bB);
            }
        }
    }

    const float inv0 = 1.f / Ol[0], inv1 = 1.f / Ol[2];
    const int b = bh >> 4, h = bh & 15;
    __half* base = g_att + ((size_t)(b*TSEQ + q0 + r0))*CDIM + h*DHEAD;
#pragma unroll
    for (int nt = 0; nt < 8; nt++) {
        *(uint32_t*)(base + nt*8 + 2*ig) =
            pack_h2(O[nt][0]*inv0, O[nt][1]*inv0);
        *(uint32_t*)(base + (size_t)8*CDIM + nt*8 + 2*ig) =
            pack_h2(O[nt][2]*inv1, O[nt][3]*inv1);
    }
}

// ---------------- launch ----------------
extern "C" void kernel_launch(void* const* d_in, const int* in_sizes, int n_in,
                              void* d_out, int out_size)
{
    (void)in_sizes; (void)n_in; (void)out_size;
    const float* x     = (const float*)d_in[0];
    const float* w_qkv = (const float*)d_in[1];
    const float* b_qkv = (const float*)d_in[2];
    const float* w_out = (const float*)d_in[3];
    const float* b_out = (const float*)d_in[4];
    float* out = (float*)d_out;

    cudaFuncSetAttribute(mm_kernel,   cudaFuncAttributeMaxDynamicSharedMemorySize, MM_SMEM);
    cudaFuncSetAttribute(attn_kernel, cudaFuncAttributeMaxDynamicSharedMemorySize, AT_SMEM);

    __half *xt, *wq, *wo;
    cudaGetSymbolAddress((void**)&xt, g_xt);
    cudaGetSymbolAddress((void**)&wq, g_wq);
    cudaGetSymbolAddress((void**)&wo, g_wo);

    // 0) one-shot fp16 conversion (x) and transpose+conversion (weights -> [N][K])
    cvtx_kernel<<<(MROWS*CDIM/4 + 255)/256, 256>>>((const float4*)x, (uint2*)xt, MROWS*CDIM/4);
    cvtw_kernel<<<dim3(3072/32, 1024/32), dim3(32, 8)>>>(w_qkv, wq, 1024, 3072);
    cvtw_kernel<<<dim3(1024/32, 1024/32), dim3(32, 8)>>>(w_out, wo, 1024, 1024);

    // 1) QKV projection + bias + head-split scatter (fp16 Q/K/V, Q pre-scaled incl. log2e)
    mm_kernel<<<dim3(3072/128, MROWS/128), 256, MM_SMEM>>>(xt, wq, b_qkv, nullptr, 3072, 0);
    // 2) causal flash attention (fp16, register P-pass, ones-MMA l, h2exp2)
    attn_kernel<<<dim3(TSEQ/64, BSZ*HH), 128, AT_SMEM>>>();
    // 3) output projection + bias (fp32 out)
    mm_kernel<<<dim3(1024/128, MROWS/128), 256, MM_SMEM>>>(nullptr, wo, b_out, out, 1024, 1);
}

// round 17
// speedup vs baseline: 1.2250x; 1.0063x over previous
#include <cuda_runtime.h>
#include <cuda_fp16.h>
#include <cstdint>

#define BSZ  4
#define TSEQ 2048
#define CDIM 1024
#define HH   16
#define DHEAD 64
#define MROWS (BSZ*TSEQ)   // 8192
#define KDIM 1024

// ---------------- device scratch (allocation-free rule), all fp16 ----------------
__device__ __align__(16) __half g_q[(size_t)BSZ*HH*TSEQ*DHEAD];
__device__ __align__(16) __half g_k[(size_t)BSZ*HH*TSEQ*DHEAD];
__device__ __align__(16) __half g_v[(size_t)BSZ*HH*TSEQ*DHEAD];
__device__ __align__(16) __half g_att[(size_t)MROWS*CDIM];
__device__ __align__(16) __half g_xt[(size_t)MROWS*CDIM];       // x, fp16
__device__ __align__(16) __half g_wq[(size_t)3*CDIM*KDIM];      // w_qkv^T [N][K] fp16
__device__ __align__(16) __half g_wo[(size_t)CDIM*KDIM];        // w_out^T [N][K] fp16

// ---------------- helpers ----------------
__device__ __forceinline__ void mma16(float* d, const uint32_t* a, const uint32_t* b) {
    asm("mma.sync.aligned.m16n8k16.row.col.f32.f16.f16.f32 "
        "{%0,%1,%2,%3}, {%4,%5,%6,%7}, {%8,%9}, {%0,%1,%2,%3};"
        : "+f"(d[0]), "+f"(d[1]), "+f"(d[2]), "+f"(d[3])
        : "r"(a[0]), "r"(a[1]), "r"(a[2]), "r"(a[3]), "r"(b[0]), "r"(b[1]));
}

__device__ __forceinline__ void ldsm4(uint32_t& r0, uint32_t& r1, uint32_t& r2, uint32_t& r3,
                                      uint32_t addr) {
    asm volatile("ldmatrix.sync.aligned.m8n8.x4.shared.b16 {%0,%1,%2,%3}, [%4];"
                 : "=r"(r0), "=r"(r1), "=r"(r2), "=r"(r3) : "r"(addr));
}

__device__ __forceinline__ void ldsm4t(uint32_t& r0, uint32_t& r1, uint32_t& r2, uint32_t& r3,
                                       uint32_t addr) {
    asm volatile("ldmatrix.sync.aligned.m8n8.x4.trans.shared.b16 {%0,%1,%2,%3}, [%4];"
                 : "=r"(r0), "=r"(r1), "=r"(r2), "=r"(r3) : "r"(addr));
}

__device__ __forceinline__ uint32_t smem_u32(const void* p) {
    uint32_t a;
    asm("{ .reg .u64 t; cvta.to.shared.u64 t, %1; cvt.u32.u64 %0, t; }" : "=r"(a) : "l"(p));
    return a;
}

__device__ __forceinline__ void cp16(uint32_t s, const void* g) {
    asm volatile("cp.async.cg.shared.global [%0], [%1], 16;" :: "r"(s), "l"(g));
}

// ---- mbarrier primitives (sm_80-class) ----
#define MBAR_INIT(addr, cnt) \
    asm volatile("mbarrier.init.shared.b64 [%0], %1;" :: "r"((uint32_t)(addr)), "r"((uint32_t)(cnt)) : "memory")
#define MBAR_ARRIVE(addr) \
    asm volatile("mbarrier.arrive.shared.b64 _, [%0];" :: "r"((uint32_t)(addr)) : "memory")
// NOINC is load-bearing: default cp.async.mbarrier.arrive increments the pending
// count (net-zero vs the fixed expected arrivals) and deadlocks the barrier.
#define CPASYNC_MBAR_ARRIVE(addr) \
    asm volatile("cp.async.mbarrier.arrive.noinc.shared.b64 [%0];" :: "r"((uint32_t)(addr)) : "memory")
#define MBAR_WAIT(addr, parity) do {                                              \
    uint32_t _m = (uint32_t)(addr); uint32_t _p = (uint32_t)(parity);             \
    asm volatile(                                                                 \
        "{\n\t.reg .pred P1;\n\t"                                                 \
        "WL_%=:\n\t"                                                              \
        "mbarrier.try_wait.parity.acquire.cta.shared::cta.b64 P1, [%0], %1, 0x989680;\n\t" \
        "@P1 bra.uni WD_%=;\n\t"                                                  \
        "bra.uni WL_%=;\n\t"                                                      \
        "WD_%=:\n\t}"                                                             \
        :: "r"(_m), "r"(_p) : "memory");                                          \
} while (0)

__device__ __forceinline__ uint32_t pack_h2(float a, float b) {
    __half2 h = __floats2half2_rn(a, b);
    return *(uint32_t*)&h;
}

__device__ __forceinline__ uint32_t h2exp2_pack(float a, float b) {
    __half2 h = h2exp2(__floats2half2_rn(a, b));
    return *(uint32_t*)&h;
}

// ---------------- x: f32 -> f16 ----------------
__global__ __launch_bounds__(256)
void cvtx_kernel(const float4* __restrict__ src, uint2* __restrict__ dst, int n4)
{
    const int i = blockIdx.x * 256 + threadIdx.x;
    if (i < n4) {
        float4 v = src[i];
        dst[i] = make_uint2(pack_h2(v.x, v.y), pack_h2(v.z, v.w));
    }
}

// ---------------- weight: f32 [R][C] -> f16 transposed [C][R] ----------------
__global__ __launch_bounds__(256)
void cvtw_kernel(const float* __restrict__ src, __half* __restrict__ dst, int R, int C)
{
    __shared__ float t[32][33];
    const int c0 = blockIdx.x * 32, r0 = blockIdx.y * 32;
    const int tx = threadIdx.x, ty = threadIdx.y;
#pragma unroll
    for (int i = 0; i < 4; i++)
        t[ty + 8*i][tx] = src[(size_t)(r0 + ty + 8*i) * C + c0 + tx];
    __syncthreads();
#pragma unroll
    for (int i = 0; i < 4; i++)
        dst[(size_t)(c0 + ty + 8*i) * R + r0 + tx] = __float2half_rn(t[tx][ty + 8*i]);
}

// ---------------- fp16 mma.sync GEMM: mbarrier-phased 3-stage pipeline (unchanged R16) ----------------
#define BK 64
#define MA_STR 72
#define MA_H (128*MA_STR)               // 9216 halves per tile
#define ST_H (2*MA_H)                   // 18432 halves = 36864 B
#define STAGES 3
#define HDR_H 64                        // 128 B header (6 mbarriers)
#define MM_SMEM ((HDR_H + STAGES*ST_H)*2)   // 110720 B

__global__ __launch_bounds__(256, 2)
void mm_kernel(const __half* __restrict__ A, const __half* __restrict__ Bt,
               const float* __restrict__ bias, float* __restrict__ Cout,
               int N, int mode)
{
    extern __shared__ __half smh[];
    const uint32_t sb  = smem_u32(smh);          // mbarrier header base
    const uint32_t sd  = sb + HDR_H*2;           // stage data base (bytes)

    const int tid  = threadIdx.x;
    const int lane = tid & 31;
    const int warp = tid >> 5;
    const int wm = (warp >> 2) * 64;
    const int wn = (warp & 3) * 32;
    const int g  = lane >> 2;
    const int ig = lane & 3;

    const int m0 = blockIdx.y * 128;
    const int n0 = blockIdx.x * 128;

    if (mode) A = g_att;

    const uint32_t aoff = ((wm + (lane & 15)) * MA_STR + (lane >> 4) * 8) * 2;
    const uint32_t boff = ((wn + (lane & 15)) * MA_STR + (lane >> 4) * 8) * 2;

    if (tid == 0) {
#pragma unroll
        for (int s = 0; s < STAGES; s++) {
            MBAR_INIT(sb + s*16,     256);
            MBAR_INIT(sb + s*16 + 8, 256);
        }
    }
    __syncthreads();

    float d[4][4][4];
#pragma unroll
    for (int mt = 0; mt < 4; mt++)
#pragma unroll
        for (int nt = 0; nt < 4; nt++)
#pragma unroll
            for (int r = 0; r < 4; r++) d[mt][nt][r] = 0.f;

#define LDG_ASYNC(c, st) do {                                                     \
    uint32_t _sa = sd + (st)*ST_H*2;                                              \
    uint32_t _sb2 = _sa + MA_H*2;                                                 \
    _Pragma("unroll") for (int i = 0; i < 4; i++) {                               \
        int idx = tid + 256*i; int row = idx >> 3, c8 = idx & 7;                  \
        cp16(_sa + (row*MA_STR + c8*8)*2,                                         \
             A + (size_t)(m0 + row)*KDIM + (c)*BK + c8*8); }                      \
    _Pragma("unroll") for (int i = 0; i < 4; i++) {                               \
        int idx = tid + 256*i; int row = idx >> 3, c8 = idx & 7;                  \
        cp16(_sb2 + (row*MA_STR + c8*8)*2,                                        \
             Bt + (size_t)(n0 + row)*KDIM + (c)*BK + c8*8); }                     \
} while (0)

#define COMPUTE(st) do {                                                          \
    const uint32_t _ab = sd + (st)*ST_H*2 + aoff;                                 \
    const uint32_t _bb = sd + (st)*ST_H*2 + MA_H*2 + boff;                        \
    _Pragma("unroll") for (int s = 0; s < 4; s++) {                               \
        const int k0 = s*16;                                                      \
        uint32_t af[4][4], bf[2][4];                                              \
        _Pragma("unroll") for (int mt = 0; mt < 4; mt++)                          \
            ldsm4(af[mt][0], af[mt][1], af[mt][2], af[mt][3],                     \
                  _ab + (mt*16*MA_STR + k0)*2);                                   \
        _Pragma("unroll") for (int p = 0; p < 2; p++)                             \
            ldsm4(bf[p][0], bf[p][1], bf[p][2], bf[p][3],                         \
                  _bb + (p*16*MA_STR + k0)*2);                                    \
        _Pragma("unroll") for (int mt = 0; mt < 4; mt++)                          \
            _Pragma("unroll") for (int p = 0; p < 2; p++) {                       \
                uint32_t b0[2] = { bf[p][0], bf[p][2] };                          \
                uint32_t b1[2] = { bf[p][1], bf[p][3] };                          \
                mma16(d[mt][2*p],   af[mt], b0);                                  \
                mma16(d[mt][2*p+1], af[mt], b1);                                  \
            }                                                                     \
    }                                                                             \
} while (0)

    // prefill chunks 0,1 (empty barriers fresh -> no wait needed)
    LDG_ASYNC(0, 0); CPASYNC_MBAR_ARRIVE(sb + 0*16);
    LDG_ASYNC(1, 1); CPASYNC_MBAR_ARRIVE(sb + 1*16);

#pragma unroll 1
    for (int c = 0; c < KDIM/BK; c++) {
        const int st = c % STAGES;
        MBAR_WAIT(sb + st*16, (c/STAGES) & 1);          // data ready
        if (c + 2 < KDIM/BK) {
            const int m = c + 2, st2 = m % STAGES;
            MBAR_WAIT(sb + st2*16 + 8, ((m/STAGES) & 1) ^ 1);   // stage free
            LDG_ASYNC(m, st2);
            CPASYNC_MBAR_ARRIVE(sb + st2*16);
        }
        COMPUTE(st);
        MBAR_ARRIVE(sb + st*16 + 8);                    // done reading stage
    }

#pragma unroll
    for (int mt = 0; mt < 4; mt++) {
        const int r0 = m0 + wm + mt*16 + g;
#pragma unroll
        for (int nt = 0; nt < 4; nt++) {
            const int c0 = n0 + wn + nt*8 + ig*2;
            const float b0 = bias[c0], b1 = bias[c0+1];
            if (mode == 0) {
                const int sec = c0 >> 10;
                const int h   = (c0 & 1023) >> 6;
                const int dd  = c0 & 63;
                __half* dstp = (sec == 0) ? g_q : ((sec == 1) ? g_k : g_v);
                // Q pre-scale folds 1/sqrt(Dh) AND log2(e) (attention works in 2^x domain)
                const float scale = (sec == 0) ? 0.125f * 1.44269504f : 1.0f;
#pragma unroll
                for (int rr = 0; rr < 2; rr++) {
                    const int r = r0 + rr*8;
                    const int b = r >> 11, t = r & 2047;
                    uint32_t v = pack_h2((d[mt][nt][rr*2+0] + b0) * scale,
                                         (d[mt][nt][rr*2+1] + b1) * scale);
                    *(uint32_t*)(dstp + (((size_t)(b*HH + h))*TSEQ + t)*DHEAD + dd) = v;
                }
            } else {
#pragma unroll
                for (int rr = 0; rr < 2; rr++) {
                    const int r = r0 + rr*8;
                    float2 v = make_float2(d[mt][nt][rr*2+0] + b0, d[mt][nt][rr*2+1] + b1);
                    *(float2*)(Cout + (size_t)r*N + c0) = v;
                }
            }
        }
    }
}

// ---------------- fp16 flash attention: mbarrier-phased K/V pipeline ----------------
// smem: [128B mbarrier header][Q][2xK][2xV] = 46208 B -> 4 CTA/SM.
#define AT_STR 72
#define T_H (64*AT_STR)                 // 4608 halves = 9216 B per tile
#define AT_HDR 64                       // 128 B header (4 mbarriers)
#define AT_SMEM ((AT_HDR + 5*T_H)*2)    // 46208 B

__global__ __launch_bounds__(128, 4)
void attn_kernel()
{
    extern __shared__ __half smh[];
    const uint32_t sb  = smem_u32(smh);              // mbarrier header
    __half* Qs  = smh + AT_HDR;
    __half* Kst = Qs + T_H;              // 2 stages
    __half* Vst = Kst + 2*T_H;           // 2 stages
    const uint32_t sb_q = smem_u32(Qs);
    const uint32_t sb_k = smem_u32(Kst);
    const uint32_t sb_v = smem_u32(Vst);

    const int tid  = threadIdx.x;
    const int lane = tid & 31;
    const int w    = tid >> 5;
    const int g    = lane >> 2;
    const int ig   = lane & 3;
    const int bh = blockIdx.y;
    const int qt = (gridDim.x - 1) - blockIdx.x;   // long blocks first
    const int q0 = qt * 64;

    const __half* Qg = g_q + (size_t)bh * TSEQ * DHEAD;
    const __half* Kg = g_k + (size_t)bh * TSEQ * DHEAD;
    const __half* Vg = g_v + (size_t)bh * TSEQ * DHEAD;

    const uint32_t aoff = ((16*w + (lane & 15)) * AT_STR + (lane >> 4) * 8) * 2;
    const uint32_t koff = (((lane & 15)) * AT_STR + (lane >> 4) * 8) * 2;

    // full[s] at sb + s*16, empty[s] at sb + s*16 + 8, s in {0,1}
    if (tid == 0) {
        MBAR_INIT(sb + 0*16,     128); MBAR_INIT(sb + 0*16 + 8, 128);
        MBAR_INIT(sb + 1*16,     128); MBAR_INIT(sb + 1*16 + 8, 128);
    }

#define PREFETCH_KV(j0, st) do {                                                  \
    uint32_t _kb = sb_k + (st)*T_H*2;                                             \
    uint32_t _vb = sb_v + (st)*T_H*2;                                             \
    _Pragma("unroll") for (int i = 0; i < 4; i++) {                               \
        int f = tid + 128*i; int row = f >> 3, c8 = f & 7;                        \
        cp16(_kb + (row*AT_STR + c8*8)*2, Kg + (size_t)((j0)+row)*DHEAD + c8*8);  \
        cp16(_vb + (row*AT_STR + c8*8)*2, Vg + (size_t)((j0)+row)*DHEAD + c8*8);  \
    }                                                                             \
} while (0)

    // Q tile: raw copy (already scaled fp16, log2 domain)
#pragma unroll
    for (int i = 0; i < 4; i++) {
        const int f = tid + 128*i;
        const int row = f >> 3, c8 = f & 7;
        *(uint4*)(Qs + row*AT_STR + c8*8) =
            *(const uint4*)(Qg + (size_t)(q0+row)*DHEAD + c8*8);
    }
    __syncthreads();            // Q visible + mbarriers initialized

    PREFETCH_KV(0, 0);
    CPASYNC_MBAR_ARRIVE(sb + 0*16);

    const int r0 = 16*w + g;
    float O[8][4];
#pragma unroll
    for (int nt = 0; nt < 8; nt++)
#pragma unroll
        for (int r = 0; r < 4; r++) O[nt][r] = 0.f;
    float Ol[4] = {0.f, 0.f, 0.f, 0.f};
    float m0 = -1e30f, m1 = -1e30f;

    const int mi  = lane >> 3;
    const int rin = lane & 7;
    const int v_row_off = ((mi & 1) ? 8 : 0) + rin;
    const int v_col_off = (mi >> 1) ? 8 : 0;

    const uint32_t ones2[2] = { 0x3C003C00u, 0x3C003C00u };   // fp16 (1,1)

#pragma unroll 1
    for (int jt = 0; jt <= qt; jt++) {
        const int j0 = jt * 64;
        const int st = jt & 1;

        MBAR_WAIT(sb + st*16, (jt >> 1) & 1);           // K/V tile jt ready

        if (jt < qt) {
            const int m = jt + 1, st2 = m & 1;
            MBAR_WAIT(sb + st2*16 + 8, ((m >> 1) & 1) ^ 1);   // stage free
            PREFETCH_KV(m*64, st2);
            CPASYNC_MBAR_ARRIVE(sb + st2*16);
        }

        const uint32_t kbase = sb_k + st*T_H*2 + koff;
        const uint32_t vbase = sb_v + st*T_H*2;

        // S = Q K^T  (16x64 per warp) — ldmatrix frags; s in log2 scale
        float s[8][4];
#pragma unroll
        for (int nt = 0; nt < 8; nt++)
#pragma unroll
            for (int r = 0; r < 4; r++) s[nt][r] = 0.f;

#pragma unroll
        for (int k0 = 0; k0 < 64; k0 += 16) {
            uint32_t a[4];
            ldsm4(a[0], a[1], a[2], a[3], sb_q + aoff + k0*2);
#pragma unroll
            for (int pp = 0; pp < 4; pp++) {
                uint32_t bf0, bf1, bf2, bf3;
                ldsm4(bf0, bf1, bf2, bf3, kbase + (pp*16*AT_STR + k0)*2);
                uint32_t b0[2] = { bf0, bf2 };
                uint32_t b1[2] = { bf1, bf3 };
                mma16(s[2*pp],   a, b0);
                mma16(s[2*pp+1], a, b1);
            }
        }

        if (jt == qt) {
            const int qa = q0 + r0, qb = qa + 8;
#pragma unroll
            for (int nt = 0; nt < 8; nt++) {
                const int j = j0 + nt*8 + 2*ig;
                if (j     > qa) s[nt][0] = -1e30f;
                if (j + 1 > qa) s[nt][1] = -1e30f;
                if (j     > qb) s[nt][2] = -1e30f;
                if (j + 1 > qb) s[nt][3] = -1e30f;
            }
        }

        float a0 = -1e30f, a1 = -1e30f;
#pragma unroll
        for (int nt = 0; nt < 8; nt++) {
            a0 = fmaxf(a0, fmaxf(s[nt][0], s[nt][1]));
            a1 = fmaxf(a1, fmaxf(s[nt][2], s[nt][3]));
        }
        a0 = fmaxf(a0, __shfl_xor_sync(0xFFFFFFFFu, a0, 1));
        a0 = fmaxf(a0, __shfl_xor_sync(0xFFFFFFFFu, a0, 2));
        a1 = fmaxf(a1, __shfl_xor_sync(0xFFFFFFFFu, a1, 1));
        a1 = fmaxf(a1, __shfl_xor_sync(0xFFFFFFFFu, a1, 2));

        const float mn0 = fmaxf(m0, a0), mn1 = fmaxf(m1, a1);
        const float c0 = exp2f(m0 - mn0), c1 = exp2f(m1 - mn1);
#pragma unroll
        for (int nt = 0; nt < 8; nt++) {
            O[nt][0] *= c0; O[nt][1] *= c0;
            O[nt][2] *= c1; O[nt][3] *= c1;
        }
        Ol[0] *= c0; Ol[1] *= c0; Ol[2] *= c1; Ol[3] *= c1;

        // P = 2^(s - mn) directly into A-fragment registers (fp16x2 ex2)
        uint32_t pa_lo[8], pa_hi[8];
#pragma unroll
        for (int nt = 0; nt < 8; nt++) {
            pa_lo[nt] = h2exp2_pack(s[nt][0] - mn0, s[nt][1] - mn0);
            pa_hi[nt] = h2exp2_pack(s[nt][2] - mn1, s[nt][3] - mn1);
        }
        m0 = mn0; m1 = mn1;

        // O += P @ V (register a-frags; V b-frags via ldsm4t; l via ones-MMA)
#pragma unroll
        for (int ks = 0; ks < 4; ks++) {
            const int k0 = ks*16;
            uint32_t a[4] = { pa_lo[2*ks], pa_hi[2*ks], pa_lo[2*ks+1], pa_hi[2*ks+1] };
            mma16(Ol, a, ones2);
#pragma unroll
            for (int nn = 0; nn < 4; nn++) {
                uint32_t b0, b1, b2, b3;
                ldsm4t(b0, b1, b2, b3,
                       vbase + ((k0 + v_row_off)*AT_STR + nn*16 + v_col_off)*2);
                uint32_t bA[2] = { b0, b1 };
                uint32_t bB[2] = { b2, b3 };
                mma16(O[2*nn],   a, bA);
                mma16(O[2*nn+1], a, bB);
            }
        }

        MBAR_ARRIVE(sb + st*16 + 8);                    // done reading K/V stage
    }

    const float inv0 = 1.f / Ol[0], inv1 = 1.f / Ol[2];
    const int b = bh >> 4, h = bh & 15;
    __half* base = g_att + ((size_t)(b*TSEQ + q0 + r0))*CDIM + h*DHEAD;
#pragma unroll
    for (int nt = 0; nt < 8; nt++) {
        *(uint32_t*)(base + nt*8 + 2*ig) =
            pack_h2(O[nt][0]*inv0, O[nt][1]*inv0);
        *(uint32_t*)(base + (size_t)8*CDIM + nt*8 + 2*ig) =
            pack_h2(O[nt][2]*inv1, O[nt][3]*inv1);
    }
}

// ---------------- launch ----------------
extern "C" void kernel_launch(void* const* d_in, const int* in_sizes, int n_in,
                              void* d_out, int out_size)
{
    (void)in_sizes; (void)n_in; (void)out_size;
    const float* x     = (const float*)d_in[0];
    const float* w_qkv = (const float*)d_in[1];
    const float* b_qkv = (const float*)d_in[2];
    const float* w_out = (const float*)d_in[3];
    const float* b_out = (const float*)d_in[4];
    float* out = (float*)d_out;

    cudaFuncSetAttribute(mm_kernel,   cudaFuncAttributeMaxDynamicSharedMemorySize, MM_SMEM);
    cudaFuncSetAttribute(attn_kernel, cudaFuncAttributeMaxDynamicSharedMemorySize, AT_SMEM);

    __half *xt, *wq, *wo;
    cudaGetSymbolAddress((void**)&xt, g_xt);
    cudaGetSymbolAddress((void**)&wq, g_wq);
    cudaGetSymbolAddress((void**)&wo, g_wo);

    // 0) one-shot fp16 conversion (x) and transpose+conversion (weights -> [N][K])
    cvtx_kernel<<<(MROWS*CDIM/4 + 255)/256, 256>>>((const float4*)x, (uint2*)xt, MROWS*CDIM/4);
    cvtw_kernel<<<dim3(3072/32, 1024/32), dim3(32, 8)>>>(w_qkv, wq, 1024, 3072);
    cvtw_kernel<<<dim3(1024/32, 1024/32), dim3(32, 8)>>>(w_out, wo, 1024, 1024);

    // 1) QKV projection + bias + head-split scatter (fp16 Q/K/V, Q pre-scaled incl. log2e)
    mm_kernel<<<dim3(3072/128, MROWS/128), 256, MM_SMEM>>>(xt, wq, b_qkv, nullptr, 3072, 0);
    // 2) causal flash attention (fp16, mbarrier K/V pipeline, register P-pass)
    attn_kernel<<<dim3(TSEQ/64, BSZ*HH), 128, AT_SMEM>>>();
    // 3) output projection + bias (fp32 out)
    mm_kernel<<<dim3(1024/128, MROWS/128), 256, MM_SMEM>>>(nullptr, wo, b_out, out, 1024, 1);
}